// round 1
// baseline (speedup 1.0000x reference)
#include <cuda_runtime.h>

// Problem constants
#define B_ 8
#define T_ 2048
#define E_ 1024
#define M_ (B_ * T_)   // 16384 flattened (b, t) rows

// Scratch (static __device__ arrays — the sanctioned alloc-free pattern)
__device__ float g_Q[(size_t)M_ * E_];          // 64 MB
__device__ float g_K[(size_t)M_ * E_];          // 64 MB
__device__ float g_V[(size_t)M_ * E_];          // 64 MB
__device__ float g_P[(size_t)B_ * T_ * T_];     // 134 MB (scores -> probs, in place)

// SGEMM tiling
#define BM 128
#define BN 128
#define BK 8
// 256 threads, each computes an 8x8 register micro-tile.

template <bool TRANSB>
__device__ __forceinline__ void sgemm_tile(
    const float* __restrict__ A, const float* __restrict__ B,
    int lda, int ldb, int m0, int n0, int kTiles, float (&acc)[8][8])
{
    __shared__ float As[BK][BM];
    __shared__ float Bs[BK][BN];

    const int tid  = threadIdx.x;
    const int arow = tid >> 1;          // 0..127 (tile row for A / B-transposed loads)
    const int acol = (tid & 1) * 4;     // 0 or 4 (k offset, float4)
    const int brow = tid >> 5;          // 0..7   (k row for non-transposed B loads)
    const int bcol = (tid & 31) * 4;    // 0..124 (n offset, float4)
    const int tx   = tid & 15;          // micro-tile col group
    const int ty   = tid >> 4;          // micro-tile row group

    for (int kt = 0; kt < kTiles; ++kt) {
        const int k0 = kt * BK;

        float4 av = *(const float4*)(A + (size_t)(m0 + arow) * lda + k0 + acol);
        float4 bv;
        if (TRANSB)
            bv = *(const float4*)(B + (size_t)(n0 + arow) * ldb + k0 + acol);
        else
            bv = *(const float4*)(B + (size_t)(k0 + brow) * ldb + n0 + bcol);

        As[acol + 0][arow] = av.x;
        As[acol + 1][arow] = av.y;
        As[acol + 2][arow] = av.z;
        As[acol + 3][arow] = av.w;
        if (TRANSB) {
            Bs[acol + 0][arow] = bv.x;
            Bs[acol + 1][arow] = bv.y;
            Bs[acol + 2][arow] = bv.z;
            Bs[acol + 3][arow] = bv.w;
        } else {
            *(float4*)&Bs[brow][bcol] = bv;
        }
        __syncthreads();

#pragma unroll
        for (int k = 0; k < BK; ++k) {
            float4 a0 = *(const float4*)&As[k][ty * 8];
            float4 a1 = *(const float4*)&As[k][ty * 8 + 4];
            float4 b0 = *(const float4*)&Bs[k][tx * 8];
            float4 b1 = *(const float4*)&Bs[k][tx * 8 + 4];
            float af[8] = {a0.x, a0.y, a0.z, a0.w, a1.x, a1.y, a1.z, a1.w};
            float bf[8] = {b0.x, b0.y, b0.z, b0.w, b1.x, b1.y, b1.z, b1.w};
#pragma unroll
            for (int i = 0; i < 8; ++i)
#pragma unroll
                for (int j = 0; j < 8; ++j)
                    acc[i][j] = fmaf(af[i], bf[j], acc[i][j]);
        }
        __syncthreads();
    }
}

__device__ __forceinline__ void store_tile(float* __restrict__ C, int ldc,
                                           int m0, int n0,
                                           float (&acc)[8][8], float scale)
{
    const int tid = threadIdx.x;
    const int tx  = tid & 15;
    const int ty  = tid >> 4;
#pragma unroll
    for (int i = 0; i < 8; ++i) {
        const int row = m0 + ty * 8 + i;
        float4 v0 = make_float4(acc[i][0] * scale, acc[i][1] * scale,
                                acc[i][2] * scale, acc[i][3] * scale);
        float4 v1 = make_float4(acc[i][4] * scale, acc[i][5] * scale,
                                acc[i][6] * scale, acc[i][7] * scale);
        *(float4*)(C + (size_t)row * ldc + n0 + tx * 8)     = v0;
        *(float4*)(C + (size_t)row * ldc + n0 + tx * 8 + 4) = v1;
    }
}

// -------- Kernel 1: QKV projections. out[m,f] = sum_e in[m,e] * W[f,e] (* scale)
__global__ void __launch_bounds__(256)
proj_kernel(const float* __restrict__ q, const float* __restrict__ k,
            const float* __restrict__ v,
            const float* __restrict__ Wq, const float* __restrict__ Wk,
            const float* __restrict__ Wv)
{
    const int z = blockIdx.z;
    const float* A = (z == 0) ? q : (z == 1) ? k : v;
    const float* W = (z == 0) ? Wq : (z == 1) ? Wk : Wv;
    float* C = (z == 0) ? g_Q : (z == 1) ? g_K : g_V;
    const float scale = (z < 2) ? 0.17677669529663687f : 1.0f;  // 1 / 1024^0.25

    const int m0 = blockIdx.y * BM;
    const int n0 = blockIdx.x * BN;
    float acc[8][8] = {};
    sgemm_tile<true>(A, W, E_, E_, m0, n0, E_ / BK, acc);
    store_tile(C, E_, m0, n0, acc, scale);
}

// -------- Kernel 2: S[i,j] = Q[i,:] . K[j,:]  (only blocks touching j <= i)
__global__ void __launch_bounds__(256)
scores_kernel()
{
    if (blockIdx.x > blockIdx.y) return;  // entirely above causal diagonal
    const int bz = blockIdx.z;
    const float* A  = g_Q + (size_t)bz * T_ * E_;
    const float* Bp = g_K + (size_t)bz * T_ * E_;
    float* C = g_P + (size_t)bz * T_ * T_;

    const int m0 = blockIdx.y * BM;
    const int n0 = blockIdx.x * BN;
    float acc[8][8] = {};
    sgemm_tile<true>(A, Bp, E_, E_, m0, n0, E_ / BK, acc);
    store_tile(C, T_, m0, n0, acc, 1.0f);
}

// -------- Kernel 3: causal row softmax, in place. Writes zeros above diagonal.
__global__ void __launch_bounds__(256)
softmax_kernel()
{
    const int i = blockIdx.x;
    const int b = blockIdx.y;
    float* row = g_P + ((size_t)b * T_ + i) * T_;
    const int L = i + 1;
    const int tid = threadIdx.x;

    __shared__ float red[8];

    // pass 1: max over [0, L)
    float m = -3.4e38f;
    for (int j = tid; j < L; j += 256) m = fmaxf(m, row[j]);
#pragma unroll
    for (int o = 16; o > 0; o >>= 1)
        m = fmaxf(m, __shfl_xor_sync(0xffffffffu, m, o));
    if ((tid & 31) == 0) red[tid >> 5] = m;
    __syncthreads();
    if (tid == 0) {
        float mm = red[0];
#pragma unroll
        for (int w = 1; w < 8; ++w) mm = fmaxf(mm, red[w]);
        red[0] = mm;
    }
    __syncthreads();
    m = red[0];
    __syncthreads();

    // pass 2: exp + sum (exp written back in place)
    float s = 0.0f;
    for (int j = tid; j < L; j += 256) {
        float e = __expf(row[j] - m);
        row[j] = e;
        s += e;
    }
#pragma unroll
    for (int o = 16; o > 0; o >>= 1)
        s += __shfl_xor_sync(0xffffffffu, s, o);
    if ((tid & 31) == 0) red[tid >> 5] = s;
    __syncthreads();
    if (tid == 0) {
        float ss = 0.0f;
#pragma unroll
        for (int w = 0; w < 8; ++w) ss += red[w];
        red[0] = ss;
    }
    __syncthreads();
    const float inv = 1.0f / red[0];

    // pass 3: normalize valid part, zero the masked tail (out GEMM reads it)
    for (int j = tid; j < T_; j += 256) {
        if (j < L) row[j] *= inv;
        else       row[j] = 0.0f;
    }
}

// -------- Kernel 4: O[i,c] = sum_j P[i,j] * V[j,c]; K-extent clamped to causal frontier
__global__ void __launch_bounds__(256)
out_kernel(float* __restrict__ out)
{
    const int bz = blockIdx.z;
    const int m0 = blockIdx.y * BM;
    const int n0 = blockIdx.x * BN;
    const float* A  = g_P + (size_t)bz * T_ * T_;
    const float* Bp = g_V + (size_t)bz * T_ * E_;

    float acc[8][8] = {};
    const int kTiles = (m0 + BM) / BK;  // columns j > m0+127 are all zero
    sgemm_tile<false>(A, Bp, T_, E_, m0, n0, kTiles, acc);
    store_tile(out + (size_t)bz * T_ * E_, E_, m0, n0, acc, 1.0f);
}

extern "C" void kernel_launch(void* const* d_in, const int* in_sizes, int n_in,
                              void* d_out, int out_size)
{
    const float* q  = (const float*)d_in[0];
    const float* k  = (const float*)d_in[1];
    const float* v  = (const float*)d_in[2];
    const float* Wq = (const float*)d_in[3];
    const float* Wk = (const float*)d_in[4];
    const float* Wv = (const float*)d_in[5];
    float* out = (float*)d_out;

    dim3 blk(256);
    proj_kernel<<<dim3(E_ / BN, M_ / BM, 3), blk>>>(q, k, v, Wq, Wk, Wv);
    scores_kernel<<<dim3(T_ / BN, T_ / BM, B_), blk>>>();
    softmax_kernel<<<dim3(T_, B_), blk>>>();
    out_kernel<<<dim3(E_ / BN, T_ / BM, B_), blk>>>(out);
}

// round 3
// speedup vs baseline: 2.6403x; 2.6403x over previous
#include <cuda_runtime.h>
#include <cuda_bf16.h>

#define B_ 8
#define T_ 2048
#define E_ 1024
#define M_ (B_ * T_)

#define BM 128
#define BN 128
#define BK 32
#define TB 256
#define NSTAGE 3
#define STAGE_BYTES 16384          // A 8KB + B 8KB (bf16, 64B rows)
#define QK_SCALE 0.17677669529663687f   // 1024^-0.25

// ---------------- scratch (__device__ globals: sanctioned alloc-free pattern) ----
__device__ __nv_bfloat16 g_xh[3][(size_t)M_ * E_];
__device__ __nv_bfloat16 g_xl[3][(size_t)M_ * E_];
__device__ __nv_bfloat16 g_wh[3][(size_t)E_ * E_];
__device__ __nv_bfloat16 g_wl[3][(size_t)E_ * E_];
__device__ __nv_bfloat16 g_Qh[(size_t)M_ * E_], g_Ql[(size_t)M_ * E_];
__device__ __nv_bfloat16 g_Kh[(size_t)M_ * E_], g_Kl[(size_t)M_ * E_];
__device__ float         g_Vp[(size_t)M_ * E_];
__device__ __nv_bfloat16 g_Vth[(size_t)B_ * E_ * T_], g_Vtl[(size_t)B_ * E_ * T_];
__device__ float         g_S[(size_t)B_ * T_ * T_];
__device__ __nv_bfloat16 g_Ph[(size_t)B_ * T_ * T_], g_Pl[(size_t)B_ * T_ * T_];

// ---------------- helpers ----------------
__device__ __forceinline__ unsigned smem_u32(const void* p) {
    return (unsigned)__cvta_generic_to_shared(p);
}
// 64B rows, 4x16B chunks, xor-swizzled: rows 0..7 conflict-free for ldmatrix
__device__ __forceinline__ unsigned swz64(int r, int c) {
    return (unsigned)(r * 64 + ((c ^ ((r >> 1) & 3)) * 16));
}
__device__ __forceinline__ void cp_async16(unsigned s, const void* g) {
    asm volatile("cp.async.cg.shared.global [%0], [%1], 16;" :: "r"(s), "l"(g) : "memory");
}
__device__ __forceinline__ void ldsm4(unsigned* r, unsigned addr) {
    asm volatile("ldmatrix.sync.aligned.m8n8.x4.shared.b16 {%0,%1,%2,%3}, [%4];"
                 : "=r"(r[0]), "=r"(r[1]), "=r"(r[2]), "=r"(r[3]) : "r"(addr));
}
__device__ __forceinline__ void mma16816(float* c, const unsigned* a, unsigned b0, unsigned b1) {
    asm volatile(
        "mma.sync.aligned.m16n8k16.row.col.f32.bf16.bf16.f32 "
        "{%0,%1,%2,%3}, {%4,%5,%6,%7}, {%8,%9}, {%0,%1,%2,%3};"
        : "+f"(c[0]), "+f"(c[1]), "+f"(c[2]), "+f"(c[3])
        : "r"(a[0]), "r"(a[1]), "r"(a[2]), "r"(a[3]), "r"(b0), "r"(b1));
}

// ---------------- mma.sync GEMM body ----------------
// D[m0..+128, n0..+128] = 3-pass split-bf16 (Ahi*Bhi + Ahi*Blo + Alo*Bhi)
// A: [*, lda] K-major bf16 ; B: [*, ldb] K-major bf16
// EPI 0: fp32 to Cf ; EPI 1: scale + split hi/lo bf16 to Chi/Clo
template <int EPI>
__device__ __forceinline__ void gemm_body(
    const __nv_bfloat16* __restrict__ Ahi, const __nv_bfloat16* __restrict__ Alo,
    const __nv_bfloat16* __restrict__ Bhi, const __nv_bfloat16* __restrict__ Blo,
    int lda, int ldb, int m0, int n0, int kTiles, float scale,
    float* __restrict__ Cf, __nv_bfloat16* __restrict__ Chi,
    __nv_bfloat16* __restrict__ Clo, int ldc)
{
    __shared__ __align__(128) char smem[NSTAGE * STAGE_BYTES];
    const unsigned sbase = smem_u32(smem);
    const int tid = threadIdx.x;
    const int wid = tid >> 5;
    const int lane = tid & 31;
    const int wm = wid & 1;        // 2 m-tiles of 64
    const int wn = wid >> 1;       // 4 n-tiles of 32

    // cp.async dest/source coords: 512 16B-chunks per tile, 2 per thread
    int ar[2], ac[2];
    unsigned adst[2], bdst[2];
#pragma unroll
    for (int j = 0; j < 2; ++j) {
        int idx = tid + j * TB;
        ar[j] = idx >> 2; ac[j] = idx & 3;
        adst[j] = swz64(ar[j], ac[j]);
        bdst[j] = 8192u + adst[j];
    }

    // ldmatrix source offsets within a stage
    unsigned aoff[4][2], boff[2][2];
#pragma unroll
    for (int mi = 0; mi < 4; ++mi)
#pragma unroll
        for (int ks = 0; ks < 2; ++ks)
            aoff[mi][ks] = swz64(wm * 64 + mi * 16 + (lane & 15), ks * 2 + (lane >> 4));
#pragma unroll
    for (int jp = 0; jp < 2; ++jp)
#pragma unroll
        for (int ks = 0; ks < 2; ++ks)
            boff[jp][ks] = 8192u + swz64(wn * 32 + jp * 16 + ((lane >> 4) & 1) * 8 + (lane & 7),
                                         ks * 2 + ((lane >> 3) & 1));

    float acc[4][4][4];
#pragma unroll
    for (int i = 0; i < 4; ++i)
#pragma unroll
        for (int j = 0; j < 4; ++j)
#pragma unroll
            for (int e = 0; e < 4; ++e) acc[i][j][e] = 0.0f;

    const int ITERS = 3 * kTiles;

    auto load_stage = [&](int it, int buf) {
        const int p = it / kTiles;
        const int k0 = (it % kTiles) * BK;
        const __nv_bfloat16* Ap = (p == 2) ? Alo : Ahi;
        const __nv_bfloat16* Bp = (p == 1) ? Blo : Bhi;
        const unsigned sb = sbase + buf * STAGE_BYTES;
#pragma unroll
        for (int j = 0; j < 2; ++j)
            cp_async16(sb + adst[j], Ap + (size_t)(m0 + ar[j]) * lda + k0 + ac[j] * 8);
#pragma unroll
        for (int j = 0; j < 2; ++j)
            cp_async16(sb + bdst[j], Bp + (size_t)(n0 + ar[j]) * ldb + k0 + ac[j] * 8);
    };

    load_stage(0, 0);
    asm volatile("cp.async.commit_group;" ::: "memory");
    load_stage(1, 1);
    asm volatile("cp.async.commit_group;" ::: "memory");

    for (int it = 0; it < ITERS; ++it) {
        asm volatile("cp.async.wait_group 1;" ::: "memory");
        __syncthreads();
        if (it + 2 < ITERS) load_stage(it + 2, (it + 2) % NSTAGE);
        asm volatile("cp.async.commit_group;" ::: "memory");

        const unsigned sb = sbase + (it % NSTAGE) * STAGE_BYTES;
#pragma unroll
        for (int ks = 0; ks < 2; ++ks) {
            unsigned a[4][4], b[2][4];
#pragma unroll
            for (int mi = 0; mi < 4; ++mi) ldsm4(a[mi], sb + aoff[mi][ks]);
#pragma unroll
            for (int jp = 0; jp < 2; ++jp) ldsm4(b[jp], sb + boff[jp][ks]);
#pragma unroll
            for (int mi = 0; mi < 4; ++mi)
#pragma unroll
                for (int ni = 0; ni < 4; ++ni)
                    mma16816(acc[mi][ni], a[mi],
                             b[ni >> 1][(ni & 1) * 2], b[ni >> 1][(ni & 1) * 2 + 1]);
        }
        __syncthreads();
    }

    // epilogue
    const int g = lane >> 2, tig = lane & 3;
#pragma unroll
    for (int mi = 0; mi < 4; ++mi) {
#pragma unroll
        for (int ni = 0; ni < 4; ++ni) {
            const int row = m0 + wm * 64 + mi * 16 + g;
            const int col = n0 + wn * 32 + ni * 8 + tig * 2;
#pragma unroll
            for (int h = 0; h < 2; ++h) {
                const int r = row + h * 8;
                float v0 = acc[mi][ni][2 * h + 0];
                float v1 = acc[mi][ni][2 * h + 1];
                if (EPI == 0) {
                    float2 val = make_float2(v0, v1);
                    *(float2*)(Cf + (size_t)r * ldc + col) = val;
                } else {
                    v0 *= scale; v1 *= scale;
                    __nv_bfloat16 h0 = __float2bfloat16(v0);
                    __nv_bfloat16 h1 = __float2bfloat16(v1);
                    __nv_bfloat162 hh; hh.x = h0; hh.y = h1;
                    __nv_bfloat162 ll;
                    ll.x = __float2bfloat16(v0 - __bfloat162float(h0));
                    ll.y = __float2bfloat16(v1 - __bfloat162float(h1));
                    *(__nv_bfloat162*)(Chi + (size_t)r * ldc + col) = hh;
                    *(__nv_bfloat162*)(Clo + (size_t)r * ldc + col) = ll;
                }
            }
        }
    }
}

// ---------------- kernels ----------------
__global__ void __launch_bounds__(TB)
proj_kernel()
{
    const int z = blockIdx.z;
    const int m0 = blockIdx.y * BM;
    const int n0 = blockIdx.x * BN;
    if (z == 0)
        gemm_body<1>(g_xh[0], g_xl[0], g_wh[0], g_wl[0], E_, E_, m0, n0, E_ / BK,
                     QK_SCALE, nullptr, g_Qh, g_Ql, E_);
    else if (z == 1)
        gemm_body<1>(g_xh[1], g_xl[1], g_wh[1], g_wl[1], E_, E_, m0, n0, E_ / BK,
                     QK_SCALE, nullptr, g_Kh, g_Kl, E_);
    else
        gemm_body<0>(g_xh[2], g_xl[2], g_wh[2], g_wl[2], E_, E_, m0, n0, E_ / BK,
                     1.0f, g_Vp, nullptr, nullptr, E_);
}

__global__ void __launch_bounds__(TB)
scores_kernel()
{
    if ((int)blockIdx.x > (int)blockIdx.y) return;   // fully above causal diagonal
    const int b = blockIdx.z;
    const size_t qo = (size_t)b * T_ * E_;
    gemm_body<0>(g_Qh + qo, g_Ql + qo, g_Kh + qo, g_Kl + qo, E_, E_,
                 blockIdx.y * BM, blockIdx.x * BN, E_ / BK, 1.0f,
                 g_S + (size_t)b * T_ * T_, nullptr, nullptr, T_);
}

__global__ void __launch_bounds__(TB)
out_kernel(float* __restrict__ out)
{
    const int b = blockIdx.z;
    const int m0 = blockIdx.y * BM;
    const int kT = (m0 + BM) / BK;   // causal clamp: P cols beyond m0+127 are zero
    gemm_body<0>(g_Ph + (size_t)b * T_ * T_, g_Pl + (size_t)b * T_ * T_,
                 g_Vth + (size_t)b * E_ * T_, g_Vtl + (size_t)b * E_ * T_,
                 T_, T_, m0, blockIdx.x * BN, kT, 1.0f,
                 out + (size_t)b * T_ * E_, nullptr, nullptr, E_);
}

__global__ void __launch_bounds__(256)
convert_kernel(const float* __restrict__ in, __nv_bfloat16* __restrict__ hi,
               __nv_bfloat16* __restrict__ lo, int n4)
{
    int i = blockIdx.x * blockDim.x + threadIdx.x;
    const int stride = gridDim.x * blockDim.x;
    for (; i < n4; i += stride) {
        float4 x = ((const float4*)in)[i];
        __nv_bfloat16 h0 = __float2bfloat16(x.x), h1 = __float2bfloat16(x.y);
        __nv_bfloat16 h2 = __float2bfloat16(x.z), h3 = __float2bfloat16(x.w);
        __nv_bfloat162 hh0; hh0.x = h0; hh0.y = h1;
        __nv_bfloat162 hh1; hh1.x = h2; hh1.y = h3;
        __nv_bfloat162 ll0, ll1;
        ll0.x = __float2bfloat16(x.x - __bfloat162float(h0));
        ll0.y = __float2bfloat16(x.y - __bfloat162float(h1));
        ll1.x = __float2bfloat16(x.z - __bfloat162float(h2));
        ll1.y = __float2bfloat16(x.w - __bfloat162float(h3));
        ((__nv_bfloat162*)hi)[2 * i] = hh0;
        ((__nv_bfloat162*)hi)[2 * i + 1] = hh1;
        ((__nv_bfloat162*)lo)[2 * i] = ll0;
        ((__nv_bfloat162*)lo)[2 * i + 1] = ll1;
    }
}

__global__ void __launch_bounds__(256)
transpose_v_kernel()
{
    __shared__ float tile[32][33];
    const int b = blockIdx.z;
    const int e0 = blockIdx.x * 32;
    const int t0 = blockIdx.y * 32;
    const int tx = threadIdx.x & 31;
    const int ty = threadIdx.x >> 5;   // 0..7
    const float* src = g_Vp + (size_t)b * T_ * E_;
#pragma unroll
    for (int k = 0; k < 4; ++k) {
        int i = ty + k * 8;
        tile[i][tx] = src[(size_t)(t0 + i) * E_ + e0 + tx];
    }
    __syncthreads();
    __nv_bfloat16* dh = g_Vth + (size_t)b * E_ * T_;
    __nv_bfloat16* dl = g_Vtl + (size_t)b * E_ * T_;
#pragma unroll
    for (int k = 0; k < 4; ++k) {
        int i = ty + k * 8;            // local e index
        float v = tile[tx][i];         // = Vp[t0+tx][e0+i]
        __nv_bfloat16 h = __float2bfloat16(v);
        dh[(size_t)(e0 + i) * T_ + t0 + tx] = h;
        dl[(size_t)(e0 + i) * T_ + t0 + tx] = __float2bfloat16(v - __bfloat162float(h));
    }
}

__global__ void __launch_bounds__(256)
softmax_kernel()
{
    const int i = blockIdx.x;
    const int b = blockIdx.y;
    float* row = g_S + ((size_t)b * T_ + i) * T_;
    __nv_bfloat16* ph = g_Ph + ((size_t)b * T_ + i) * T_;
    __nv_bfloat16* pl = g_Pl + ((size_t)b * T_ + i) * T_;
    const int L = i + 1;
    const int tid = threadIdx.x;
    __shared__ float red[8];

    float m = -3.4e38f;
    for (int j = tid; j < L; j += 256) m = fmaxf(m, row[j]);
#pragma unroll
    for (int o = 16; o > 0; o >>= 1) m = fmaxf(m, __shfl_xor_sync(0xffffffffu, m, o));
    if ((tid & 31) == 0) red[tid >> 5] = m;
    __syncthreads();
    if (tid == 0) {
        float mm = red[0];
#pragma unroll
        for (int w = 1; w < 8; ++w) mm = fmaxf(mm, red[w]);
        red[0] = mm;
    }
    __syncthreads();
    m = red[0];
    __syncthreads();

    float s = 0.0f;
    for (int j = tid; j < L; j += 256) {
        float e = __expf(row[j] - m);
        row[j] = e;
        s += e;
    }
#pragma unroll
    for (int o = 16; o > 0; o >>= 1) s += __shfl_xor_sync(0xffffffffu, s, o);
    if ((tid & 31) == 0) red[tid >> 5] = s;
    __syncthreads();
    if (tid == 0) {
        float ss = 0.0f;
#pragma unroll
        for (int w = 0; w < 8; ++w) ss += red[w];
        red[0] = ss;
    }
    __syncthreads();
    const float inv = 1.0f / red[0];

    for (int j = tid; j < T_; j += 256) {
        if (j < L) {
            float p = row[j] * inv;
            __nv_bfloat16 h = __float2bfloat16(p);
            ph[j] = h;
            pl[j] = __float2bfloat16(p - __bfloat162float(h));
        } else {
            ph[j] = __float2bfloat16(0.0f);
            pl[j] = __float2bfloat16(0.0f);
        }
    }
}

// ---------------- launch ----------------
extern "C" void kernel_launch(void* const* d_in, const int* in_sizes, int n_in,
                              void* d_out, int out_size)
{
    const float* q  = (const float*)d_in[0];
    const float* k  = (const float*)d_in[1];
    const float* v  = (const float*)d_in[2];
    const float* Wq = (const float*)d_in[3];
    const float* Wk = (const float*)d_in[4];
    const float* Wv = (const float*)d_in[5];
    float* out = (float*)d_out;

    __nv_bfloat16 *xh0, *xl0, *wh0, *wl0;
    cudaGetSymbolAddress((void**)&xh0, g_xh);
    cudaGetSymbolAddress((void**)&xl0, g_xl);
    cudaGetSymbolAddress((void**)&wh0, g_wh);
    cudaGetSymbolAddress((void**)&wl0, g_wl);
    __nv_bfloat16 *xh1 = xh0 + (size_t)M_ * E_, *xh2 = xh1 + (size_t)M_ * E_;
    __nv_bfloat16 *xl1 = xl0 + (size_t)M_ * E_, *xl2 = xl1 + (size_t)M_ * E_;
    __nv_bfloat16 *wh1 = wh0 + (size_t)E_ * E_, *wh2 = wh1 + (size_t)E_ * E_;
    __nv_bfloat16 *wl1 = wl0 + (size_t)E_ * E_, *wl2 = wl1 + (size_t)E_ * E_;

    const int n4x = M_ * E_ / 4;
    const int n4w = E_ * E_ / 4;
    convert_kernel<<<4096, 256>>>(q,  xh0, xl0, n4x);
    convert_kernel<<<4096, 256>>>(k,  xh1, xl1, n4x);
    convert_kernel<<<4096, 256>>>(v,  xh2, xl2, n4x);
    convert_kernel<<<1024, 256>>>(Wq, wh0, wl0, n4w);
    convert_kernel<<<1024, 256>>>(Wk, wh1, wl1, n4w);
    convert_kernel<<<1024, 256>>>(Wv, wh2, wl2, n4w);

    proj_kernel<<<dim3(E_ / BN, M_ / BM, 3), TB>>>();
    transpose_v_kernel<<<dim3(E_ / 32, T_ / 32, B_), 256>>>();
    scores_kernel<<<dim3(T_ / BN, T_ / BM, B_), TB>>>();
    softmax_kernel<<<dim3(T_, B_), 256>>>();
    out_kernel<<<dim3(E_ / BN, T_ / BM, B_), TB>>>(out);
}

// round 4
// speedup vs baseline: 3.3614x; 1.2731x over previous
#include <cuda_runtime.h>
#include <cuda_bf16.h>

#define B_ 8
#define T_ 2048
#define E_ 1024
#define M_ (B_ * T_)

#define BM 128
#define BN 128
#define BK 64
#define TB 256
#define NSTAGE 3
#define SUBT 16384u                      // one 128x64 bf16 subtile
#define STAGE_BYTES (4 * SUBT)           // Ahi, Alo, Bhi, Blo
#define DSMEM (NSTAGE * STAGE_BYTES)     // 196608
#define QK_SCALE 0.17677669529663687f    // 1024^-0.25

// ---------------- scratch ----------------
__device__ __nv_bfloat16 g_xh[3][(size_t)M_ * E_];
__device__ __nv_bfloat16 g_xl[3][(size_t)M_ * E_];
__device__ __nv_bfloat16 g_wh[3][(size_t)E_ * E_];
__device__ __nv_bfloat16 g_wl[3][(size_t)E_ * E_];
__device__ __nv_bfloat16 g_Qh[(size_t)M_ * E_], g_Ql[(size_t)M_ * E_];
__device__ __nv_bfloat16 g_Kh[(size_t)M_ * E_], g_Kl[(size_t)M_ * E_];
__device__ float         g_Vp[(size_t)M_ * E_];
__device__ __nv_bfloat16 g_Vth[(size_t)B_ * E_ * T_], g_Vtl[(size_t)B_ * E_ * T_];
__device__ float         g_S[(size_t)B_ * T_ * T_];
__device__ __nv_bfloat16 g_Ph[(size_t)B_ * T_ * T_], g_Pl[(size_t)B_ * T_ * T_];

// ---------------- helpers ----------------
__device__ __forceinline__ unsigned smem_u32(const void* p) {
    return (unsigned)__cvta_generic_to_shared(p);
}
// 128B rows, 8x16B chunks, SW128 xor swizzle: conflict-free for ldmatrix
__device__ __forceinline__ unsigned swz128(int r, int c) {
    return (unsigned)(r * 128 + ((c ^ (r & 7)) * 16));
}
__device__ __forceinline__ void cp_async16(unsigned s, const void* g) {
    asm volatile("cp.async.cg.shared.global [%0], [%1], 16;" :: "r"(s), "l"(g) : "memory");
}
__device__ __forceinline__ void ldsm4(unsigned* r, unsigned addr) {
    asm volatile("ldmatrix.sync.aligned.m8n8.x4.shared.b16 {%0,%1,%2,%3}, [%4];"
                 : "=r"(r[0]), "=r"(r[1]), "=r"(r[2]), "=r"(r[3]) : "r"(addr));
}
__device__ __forceinline__ void mma16816(float* c, const unsigned* a, unsigned b0, unsigned b1) {
    asm volatile(
        "mma.sync.aligned.m16n8k16.row.col.f32.bf16.bf16.f32 "
        "{%0,%1,%2,%3}, {%4,%5,%6,%7}, {%8,%9}, {%0,%1,%2,%3};"
        : "+f"(c[0]), "+f"(c[1]), "+f"(c[2]), "+f"(c[3])
        : "r"(a[0]), "r"(a[1]), "r"(a[2]), "r"(a[3]), "r"(b0), "r"(b1));
}

// ---------------- fused 3-pass mma.sync GEMM body ----------------
// D[m0..+128, n0..+128] = Ahi*Bhi + Alo*Bhi + Ahi*Blo   (split-bf16)
// A: [*, lda] K-major bf16 ; B: [*, ldb] K-major bf16
// EPI 0: fp32 to Cf ; EPI 1: scale + split hi/lo bf16 to Chi/Clo
template <int EPI>
__device__ __forceinline__ void gemm_body(
    const __nv_bfloat16* __restrict__ Ahi, const __nv_bfloat16* __restrict__ Alo,
    const __nv_bfloat16* __restrict__ Bhi, const __nv_bfloat16* __restrict__ Blo,
    int lda, int ldb, int m0, int n0, int kTiles, float scale,
    float* __restrict__ Cf, __nv_bfloat16* __restrict__ Chi,
    __nv_bfloat16* __restrict__ Clo, int ldc)
{
    extern __shared__ __align__(128) char smem[];
    const unsigned sbase = smem_u32(smem);
    const int tid = threadIdx.x;
    const int wid = tid >> 5;
    const int lane = tid & 31;
    const int wm = wid & 1;        // 2 m-tiles of 64
    const int wn = wid >> 1;       // 4 n-tiles of 32

    // ldmatrix offsets within a subtile
    unsigned aoff[4][4], boff[2][4];
#pragma unroll
    for (int mi = 0; mi < 4; ++mi)
#pragma unroll
        for (int ks = 0; ks < 4; ++ks)
            aoff[mi][ks] = swz128(wm * 64 + mi * 16 + (lane & 15), ks * 2 + (lane >> 4));
#pragma unroll
    for (int jp = 0; jp < 2; ++jp)
#pragma unroll
        for (int ks = 0; ks < 4; ++ks)
            boff[jp][ks] = swz128(wn * 32 + jp * 16 + ((lane >> 4) & 1) * 8 + (lane & 7),
                                  ks * 2 + ((lane >> 3) & 1));

    float acc[4][4][4];
#pragma unroll
    for (int i = 0; i < 4; ++i)
#pragma unroll
        for (int j = 0; j < 4; ++j)
#pragma unroll
            for (int e = 0; e < 4; ++e) acc[i][j][e] = 0.0f;

    // cp.async: 4096 chunks/stage, 16 per thread; j>>2 = subtile (compile-time)
    const int cc = tid & 7;        // chunk within row (constant per thread)
    const int rr = tid >> 3;       // base row (0..31)

    auto load_stage = [&](int k0, int buf) {
        const unsigned sb = sbase + buf * STAGE_BYTES;
#pragma unroll
        for (int j = 0; j < 16; ++j) {
            const int s = j >> 2;                 // 0:Ahi 1:Alo 2:Bhi 3:Blo
            const int r = rr + (j & 3) * 32;
            const __nv_bfloat16* src = (s == 0) ? Ahi : (s == 1) ? Alo
                                     : (s == 2) ? Bhi : Blo;
            const int rowbase = (s < 2) ? m0 : n0;
            const int ld = (s < 2) ? lda : ldb;
            cp_async16(sb + s * SUBT + swz128(r, cc),
                       src + (size_t)(rowbase + r) * ld + k0 + cc * 8);
        }
    };

    auto mma_block = [&](unsigned (&a)[4][4], unsigned (&b)[2][4]) {
#pragma unroll
        for (int mi = 0; mi < 4; ++mi)
#pragma unroll
            for (int ni = 0; ni < 4; ++ni)
                mma16816(acc[mi][ni], a[mi],
                         b[ni >> 1][(ni & 1) * 2], b[ni >> 1][(ni & 1) * 2 + 1]);
    };

    auto compute_ks = [&](unsigned sb, int ks) {
        unsigned ah[4][4], bh[2][4];
#pragma unroll
        for (int mi = 0; mi < 4; ++mi) ldsm4(ah[mi], sb + aoff[mi][ks]);
#pragma unroll
        for (int jp = 0; jp < 2; ++jp) ldsm4(bh[jp], sb + 2 * SUBT + boff[jp][ks]);
        mma_block(ah, bh);
        {
            unsigned al[4][4];
#pragma unroll
            for (int mi = 0; mi < 4; ++mi) ldsm4(al[mi], sb + SUBT + aoff[mi][ks]);
            mma_block(al, bh);
        }
        {
            unsigned bl[2][4];
#pragma unroll
            for (int jp = 0; jp < 2; ++jp) ldsm4(bl[jp], sb + 3 * SUBT + boff[jp][ks]);
            mma_block(ah, bl);
        }
    };

    load_stage(0, 0);
    asm volatile("cp.async.commit_group;" ::: "memory");
    if (kTiles > 1) load_stage(BK, 1);
    asm volatile("cp.async.commit_group;" ::: "memory");

    for (int it = 0; it < kTiles; ++it) {
        asm volatile("cp.async.wait_group 1;" ::: "memory");
        __syncthreads();
        const unsigned sb = sbase + (it % NSTAGE) * STAGE_BYTES;
        compute_ks(sb, 0);
        if (it + 2 < kTiles) load_stage((it + 2) * BK, (it + 2) % NSTAGE);
        asm volatile("cp.async.commit_group;" ::: "memory");
        compute_ks(sb, 1);
        compute_ks(sb, 2);
        compute_ks(sb, 3);
    }

    // epilogue
    const int g = lane >> 2, tig = lane & 3;
#pragma unroll
    for (int mi = 0; mi < 4; ++mi) {
#pragma unroll
        for (int ni = 0; ni < 4; ++ni) {
            const int row = m0 + wm * 64 + mi * 16 + g;
            const int col = n0 + wn * 32 + ni * 8 + tig * 2;
#pragma unroll
            for (int h = 0; h < 2; ++h) {
                const int r = row + h * 8;
                float v0 = acc[mi][ni][2 * h + 0];
                float v1 = acc[mi][ni][2 * h + 1];
                if (EPI == 0) {
                    *(float2*)(Cf + (size_t)r * ldc + col) = make_float2(v0, v1);
                } else {
                    v0 *= scale; v1 *= scale;
                    __nv_bfloat16 h0 = __float2bfloat16(v0);
                    __nv_bfloat16 h1 = __float2bfloat16(v1);
                    __nv_bfloat162 hh; hh.x = h0; hh.y = h1;
                    __nv_bfloat162 ll;
                    ll.x = __float2bfloat16(v0 - __bfloat162float(h0));
                    ll.y = __float2bfloat16(v1 - __bfloat162float(h1));
                    *(__nv_bfloat162*)(Chi + (size_t)r * ldc + col) = hh;
                    *(__nv_bfloat162*)(Clo + (size_t)r * ldc + col) = ll;
                }
            }
        }
    }
}

// ---------------- kernels ----------------
__global__ void __launch_bounds__(TB, 1)
proj_kernel()
{
    const int z = blockIdx.z;
    const int m0 = blockIdx.y * BM;
    const int n0 = blockIdx.x * BN;
    if (z == 0)
        gemm_body<1>(g_xh[0], g_xl[0], g_wh[0], g_wl[0], E_, E_, m0, n0, E_ / BK,
                     QK_SCALE, nullptr, g_Qh, g_Ql, E_);
    else if (z == 1)
        gemm_body<1>(g_xh[1], g_xl[1], g_wh[1], g_wl[1], E_, E_, m0, n0, E_ / BK,
                     QK_SCALE, nullptr, g_Kh, g_Kl, E_);
    else
        gemm_body<0>(g_xh[2], g_xl[2], g_wh[2], g_wl[2], E_, E_, m0, n0, E_ / BK,
                     1.0f, g_Vp, nullptr, nullptr, E_);
}

__global__ void __launch_bounds__(TB, 1)
scores_kernel()
{
    if ((int)blockIdx.x > (int)blockIdx.y) return;   // fully above causal diagonal
    const int b = blockIdx.z;
    const size_t qo = (size_t)b * T_ * E_;
    gemm_body<0>(g_Qh + qo, g_Ql + qo, g_Kh + qo, g_Kl + qo, E_, E_,
                 blockIdx.y * BM, blockIdx.x * BN, E_ / BK, 1.0f,
                 g_S + (size_t)b * T_ * T_, nullptr, nullptr, T_);
}

__global__ void __launch_bounds__(TB, 1)
out_kernel(float* __restrict__ out)
{
    const int b = blockIdx.z;
    const int m0 = blockIdx.y * BM;
    const int kT = (m0 + BM) / BK;   // causal clamp: P cols beyond m0+127 are zero
    gemm_body<0>(g_Ph + (size_t)b * T_ * T_, g_Pl + (size_t)b * T_ * T_,
                 g_Vth + (size_t)b * E_ * T_, g_Vtl + (size_t)b * E_ * T_,
                 T_, T_, m0, blockIdx.x * BN, kT, 1.0f,
                 out + (size_t)b * T_ * E_, nullptr, nullptr, E_);
}

__global__ void __launch_bounds__(256)
convert_kernel(const float* __restrict__ in, __nv_bfloat16* __restrict__ hi,
               __nv_bfloat16* __restrict__ lo, int n4)
{
    int i = blockIdx.x * blockDim.x + threadIdx.x;
    const int stride = gridDim.x * blockDim.x;
    for (; i < n4; i += stride) {
        float4 x = ((const float4*)in)[i];
        __nv_bfloat16 h0 = __float2bfloat16(x.x), h1 = __float2bfloat16(x.y);
        __nv_bfloat16 h2 = __float2bfloat16(x.z), h3 = __float2bfloat16(x.w);
        __nv_bfloat162 hh0; hh0.x = h0; hh0.y = h1;
        __nv_bfloat162 hh1; hh1.x = h2; hh1.y = h3;
        __nv_bfloat162 ll0, ll1;
        ll0.x = __float2bfloat16(x.x - __bfloat162float(h0));
        ll0.y = __float2bfloat16(x.y - __bfloat162float(h1));
        ll1.x = __float2bfloat16(x.z - __bfloat162float(h2));
        ll1.y = __float2bfloat16(x.w - __bfloat162float(h3));
        ((__nv_bfloat162*)hi)[2 * i] = hh0;
        ((__nv_bfloat162*)hi)[2 * i + 1] = hh1;
        ((__nv_bfloat162*)lo)[2 * i] = ll0;
        ((__nv_bfloat162*)lo)[2 * i + 1] = ll1;
    }
}

__global__ void __launch_bounds__(256)
transpose_v_kernel()
{
    __shared__ float tile[32][33];
    const int b = blockIdx.z;
    const int e0 = blockIdx.x * 32;
    const int t0 = blockIdx.y * 32;
    const int tx = threadIdx.x & 31;
    const int ty = threadIdx.x >> 5;
    const float* src = g_Vp + (size_t)b * T_ * E_;
#pragma unroll
    for (int k = 0; k < 4; ++k) {
        int i = ty + k * 8;
        tile[i][tx] = src[(size_t)(t0 + i) * E_ + e0 + tx];
    }
    __syncthreads();
    __nv_bfloat16* dh = g_Vth + (size_t)b * E_ * T_;
    __nv_bfloat16* dl = g_Vtl + (size_t)b * E_ * T_;
#pragma unroll
    for (int k = 0; k < 4; ++k) {
        int i = ty + k * 8;
        float v = tile[tx][i];
        __nv_bfloat16 h = __float2bfloat16(v);
        dh[(size_t)(e0 + i) * T_ + t0 + tx] = h;
        dl[(size_t)(e0 + i) * T_ + t0 + tx] = __float2bfloat16(v - __bfloat162float(h));
    }
}

__global__ void __launch_bounds__(256)
softmax_kernel()
{
    const int i = blockIdx.x;
    const int b = blockIdx.y;
    float* row = g_S + ((size_t)b * T_ + i) * T_;
    __nv_bfloat16* ph = g_Ph + ((size_t)b * T_ + i) * T_;
    __nv_bfloat16* pl = g_Pl + ((size_t)b * T_ + i) * T_;
    const int L = i + 1;
    const int tid = threadIdx.x;
    __shared__ float red[8];

    float m = -3.4e38f;
    for (int j = tid; j < L; j += 256) m = fmaxf(m, row[j]);
#pragma unroll
    for (int o = 16; o > 0; o >>= 1) m = fmaxf(m, __shfl_xor_sync(0xffffffffu, m, o));
    if ((tid & 31) == 0) red[tid >> 5] = m;
    __syncthreads();
    if (tid == 0) {
        float mm = red[0];
#pragma unroll
        for (int w = 1; w < 8; ++w) mm = fmaxf(mm, red[w]);
        red[0] = mm;
    }
    __syncthreads();
    m = red[0];
    __syncthreads();

    float s = 0.0f;
    for (int j = tid; j < L; j += 256) {
        float e = __expf(row[j] - m);
        row[j] = e;
        s += e;
    }
#pragma unroll
    for (int o = 16; o > 0; o >>= 1) s += __shfl_xor_sync(0xffffffffu, s, o);
    if ((tid & 31) == 0) red[tid >> 5] = s;
    __syncthreads();
    if (tid == 0) {
        float ss = 0.0f;
#pragma unroll
        for (int w = 0; w < 8; ++w) ss += red[w];
        red[0] = ss;
    }
    __syncthreads();
    const float inv = 1.0f / red[0];

    for (int j = tid; j < T_; j += 256) {
        if (j < L) {
            float p = row[j] * inv;
            __nv_bfloat16 h = __float2bfloat16(p);
            ph[j] = h;
            pl[j] = __float2bfloat16(p - __bfloat162float(h));
        } else {
            ph[j] = __float2bfloat16(0.0f);
            pl[j] = __float2bfloat16(0.0f);
        }
    }
}

// ---------------- launch ----------------
extern "C" void kernel_launch(void* const* d_in, const int* in_sizes, int n_in,
                              void* d_out, int out_size)
{
    const float* q  = (const float*)d_in[0];
    const float* k  = (const float*)d_in[1];
    const float* v  = (const float*)d_in[2];
    const float* Wq = (const float*)d_in[3];
    const float* Wk = (const float*)d_in[4];
    const float* Wv = (const float*)d_in[5];
    float* out = (float*)d_out;

    static int attr_done = 0;
    if (!attr_done) {
        cudaFuncSetAttribute(proj_kernel,   cudaFuncAttributeMaxDynamicSharedMemorySize, DSMEM);
        cudaFuncSetAttribute(scores_kernel, cudaFuncAttributeMaxDynamicSharedMemorySize, DSMEM);
        cudaFuncSetAttribute(out_kernel,    cudaFuncAttributeMaxDynamicSharedMemorySize, DSMEM);
        attr_done = 1;
    }

    __nv_bfloat16 *xh0, *xl0, *wh0, *wl0;
    cudaGetSymbolAddress((void**)&xh0, g_xh);
    cudaGetSymbolAddress((void**)&xl0, g_xl);
    cudaGetSymbolAddress((void**)&wh0, g_wh);
    cudaGetSymbolAddress((void**)&wl0, g_wl);
    __nv_bfloat16 *xh1 = xh0 + (size_t)M_ * E_, *xh2 = xh1 + (size_t)M_ * E_;
    __nv_bfloat16 *xl1 = xl0 + (size_t)M_ * E_, *xl2 = xl1 + (size_t)M_ * E_;
    __nv_bfloat16 *wh1 = wh0 + (size_t)E_ * E_, *wh2 = wh1 + (size_t)E_ * E_;
    __nv_bfloat16 *wl1 = wl0 + (size_t)E_ * E_, *wl2 = wl1 + (size_t)E_ * E_;

    const int n4x = M_ * E_ / 4;
    const int n4w = E_ * E_ / 4;
    convert_kernel<<<2048, 256>>>(q,  xh0, xl0, n4x);
    convert_kernel<<<2048, 256>>>(k,  xh1, xl1, n4x);
    convert_kernel<<<2048, 256>>>(v,  xh2, xl2, n4x);
    convert_kernel<<<512, 256>>>(Wq, wh0, wl0, n4w);
    convert_kernel<<<512, 256>>>(Wk, wh1, wl1, n4w);
    convert_kernel<<<512, 256>>>(Wv, wh2, wl2, n4w);

    proj_kernel<<<dim3(E_ / BN, M_ / BM, 3), TB, DSMEM>>>();
    transpose_v_kernel<<<dim3(E_ / 32, T_ / 32, B_), 256>>>();
    scores_kernel<<<dim3(T_ / BN, T_ / BM, B_), TB, DSMEM>>>();
    softmax_kernel<<<dim3(T_, B_), 256>>>();
    out_kernel<<<dim3(E_ / BN, T_ / BM, B_), TB, DSMEM>>>(out);
}

// round 5
// speedup vs baseline: 4.3553x; 1.2957x over previous
#include <cuda_runtime.h>
#include <cuda_fp16.h>

#define B_ 8
#define T_ 2048
#define E_ 1024
#define M_ (B_ * T_)

#define BM 128
#define BN 128
#define BK 64
#define TB 256
#define NSTAGE 3
#define SUBT 16384u                      // one 128x64 fp16 subtile
#define STAGE_BYTES (3 * SUBT)           // Ah, Al, B
#define DSMEM (NSTAGE * STAGE_BYTES)     // 147456
#define QK_SCALE 0.17677669529663687f    // 1024^-0.25

// ---------------- scratch ----------------
__device__ __half g_xh[3][(size_t)M_ * E_];
__device__ __half g_xl[3][(size_t)M_ * E_];
__device__ __half g_w[3][(size_t)E_ * E_];
__device__ __half g_Qh[(size_t)M_ * E_], g_Ql[(size_t)M_ * E_];
__device__ __half g_Kh[(size_t)M_ * E_];
__device__ __half g_Vh[(size_t)M_ * E_];
__device__ __half g_Vt[(size_t)B_ * E_ * T_];
__device__ float  g_S[(size_t)B_ * T_ * T_];
__device__ __half g_Ph[(size_t)B_ * T_ * T_], g_Pl[(size_t)B_ * T_ * T_];

// ---------------- helpers ----------------
__device__ __forceinline__ unsigned smem_u32(const void* p) {
    return (unsigned)__cvta_generic_to_shared(p);
}
// 128B rows, 8x16B chunks, SW128 xor swizzle: conflict-free for ldmatrix
__device__ __forceinline__ unsigned swz128(int r, int c) {
    return (unsigned)(r * 128 + ((c ^ (r & 7)) * 16));
}
__device__ __forceinline__ void cp_async16(unsigned s, const void* g) {
    asm volatile("cp.async.cg.shared.global [%0], [%1], 16;" :: "r"(s), "l"(g) : "memory");
}
__device__ __forceinline__ void ldsm4(unsigned* r, unsigned addr) {
    asm volatile("ldmatrix.sync.aligned.m8n8.x4.shared.b16 {%0,%1,%2,%3}, [%4];"
                 : "=r"(r[0]), "=r"(r[1]), "=r"(r[2]), "=r"(r[3]) : "r"(addr));
}
__device__ __forceinline__ void mma16816(float* c, const unsigned* a, unsigned b0, unsigned b1) {
    asm volatile(
        "mma.sync.aligned.m16n8k16.row.col.f32.f16.f16.f32 "
        "{%0,%1,%2,%3}, {%4,%5,%6,%7}, {%8,%9}, {%0,%1,%2,%3};"
        : "+f"(c[0]), "+f"(c[1]), "+f"(c[2]), "+f"(c[3])
        : "r"(a[0]), "r"(a[1]), "r"(a[2]), "r"(a[3]), "r"(b0), "r"(b1));
}

// ---------------- fused 2-pass mma.sync GEMM body ----------------
// D[m0..+128, n0..+128] = Ah*B + Al*B    (A split across two fp16, B single fp16)
// EPI 0: fp32 to Cf ; EPI 1: scale + split hi/lo fp16 to Chi/Clo ; EPI 2: scale + fp16 to Chi
template <int EPI>
__device__ __forceinline__ void gemm_body(
    const __half* __restrict__ Ah, const __half* __restrict__ Al,
    const __half* __restrict__ Bs,
    int lda, int ldb, int m0, int n0, int kTiles, float scale,
    float* __restrict__ Cf, __half* __restrict__ Chi,
    __half* __restrict__ Clo, int ldc)
{
    extern __shared__ __align__(128) char smem[];
    const unsigned sbase = smem_u32(smem);
    const int tid = threadIdx.x;
    const int wid = tid >> 5;
    const int lane = tid & 31;
    const int wm = wid & 1;        // 2 m-tiles of 64
    const int wn = wid >> 1;       // 4 n-tiles of 32

    // ldmatrix offsets within a subtile
    unsigned aoff[4][4], boff[2][4];
#pragma unroll
    for (int mi = 0; mi < 4; ++mi)
#pragma unroll
        for (int ks = 0; ks < 4; ++ks)
            aoff[mi][ks] = swz128(wm * 64 + mi * 16 + (lane & 15), ks * 2 + (lane >> 4));
#pragma unroll
    for (int jp = 0; jp < 2; ++jp)
#pragma unroll
        for (int ks = 0; ks < 4; ++ks)
            boff[jp][ks] = swz128(wn * 32 + jp * 16 + ((lane >> 4) & 1) * 8 + (lane & 7),
                                  ks * 2 + ((lane >> 3) & 1));

    float acc[4][4][4];
#pragma unroll
    for (int i = 0; i < 4; ++i)
#pragma unroll
        for (int j = 0; j < 4; ++j)
#pragma unroll
            for (int e = 0; e < 4; ++e) acc[i][j][e] = 0.0f;

    const int cc = tid & 7;        // chunk within row
    const int rr = tid >> 3;       // base row (0..31)

    auto load_stage = [&](int k0, int buf) {
        const unsigned sb = sbase + buf * STAGE_BYTES;
#pragma unroll
        for (int j = 0; j < 12; ++j) {
            const int s = j >> 2;                 // 0:Ah 1:Al 2:B
            const int r = rr + (j & 3) * 32;
            const __half* src = (s == 0) ? Ah : (s == 1) ? Al : Bs;
            const int rowbase = (s < 2) ? m0 : n0;
            const int ld = (s < 2) ? lda : ldb;
            cp_async16(sb + s * SUBT + swz128(r, cc),
                       src + (size_t)(rowbase + r) * ld + k0 + cc * 8);
        }
    };

    auto mma_block = [&](unsigned (&a)[4][4], unsigned (&b)[2][4]) {
#pragma unroll
        for (int mi = 0; mi < 4; ++mi)
#pragma unroll
            for (int ni = 0; ni < 4; ++ni)
                mma16816(acc[mi][ni], a[mi],
                         b[ni >> 1][(ni & 1) * 2], b[ni >> 1][(ni & 1) * 2 + 1]);
    };

    auto compute_ks = [&](unsigned sb, int ks) {
        unsigned ah[4][4], b[2][4];
#pragma unroll
        for (int mi = 0; mi < 4; ++mi) ldsm4(ah[mi], sb + aoff[mi][ks]);
#pragma unroll
        for (int jp = 0; jp < 2; ++jp) ldsm4(b[jp], sb + 2 * SUBT + boff[jp][ks]);
        mma_block(ah, b);
        {
            unsigned al[4][4];
#pragma unroll
            for (int mi = 0; mi < 4; ++mi) ldsm4(al[mi], sb + SUBT + aoff[mi][ks]);
            mma_block(al, b);
        }
    };

    load_stage(0, 0);
    asm volatile("cp.async.commit_group;" ::: "memory");
    if (kTiles > 1) load_stage(BK, 1);
    asm volatile("cp.async.commit_group;" ::: "memory");

    for (int it = 0; it < kTiles; ++it) {
        asm volatile("cp.async.wait_group 1;" ::: "memory");
        __syncthreads();
        const unsigned sb = sbase + (it % NSTAGE) * STAGE_BYTES;
        compute_ks(sb, 0);
        if (it + 2 < kTiles) load_stage((it + 2) * BK, (it + 2) % NSTAGE);
        asm volatile("cp.async.commit_group;" ::: "memory");
        compute_ks(sb, 1);
        compute_ks(sb, 2);
        compute_ks(sb, 3);
    }

    // epilogue
    const int g = lane >> 2, tig = lane & 3;
#pragma unroll
    for (int mi = 0; mi < 4; ++mi) {
#pragma unroll
        for (int ni = 0; ni < 4; ++ni) {
            const int row = m0 + wm * 64 + mi * 16 + g;
            const int col = n0 + wn * 32 + ni * 8 + tig * 2;
#pragma unroll
            for (int h = 0; h < 2; ++h) {
                const int r = row + h * 8;
                float v0 = acc[mi][ni][2 * h + 0];
                float v1 = acc[mi][ni][2 * h + 1];
                if (EPI == 0) {
                    *(float2*)(Cf + (size_t)r * ldc + col) = make_float2(v0, v1);
                } else if (EPI == 1) {
                    v0 *= scale; v1 *= scale;
                    __half h0 = __float2half(v0);
                    __half h1 = __float2half(v1);
                    __half2 hh; hh.x = h0; hh.y = h1;
                    __half2 ll;
                    ll.x = __float2half(v0 - __half2float(h0));
                    ll.y = __float2half(v1 - __half2float(h1));
                    *(__half2*)(Chi + (size_t)r * ldc + col) = hh;
                    *(__half2*)(Clo + (size_t)r * ldc + col) = ll;
                } else {
                    __half2 hh;
                    hh.x = __float2half(v0 * scale);
                    hh.y = __float2half(v1 * scale);
                    *(__half2*)(Chi + (size_t)r * ldc + col) = hh;
                }
            }
        }
    }
}

// ---------------- kernels ----------------
__global__ void __launch_bounds__(TB, 1)
proj_kernel()
{
    const int z = blockIdx.z;
    const int m0 = blockIdx.y * BM;
    const int n0 = blockIdx.x * BN;
    if (z == 0)
        gemm_body<1>(g_xh[0], g_xl[0], g_w[0], E_, E_, m0, n0, E_ / BK,
                     QK_SCALE, nullptr, g_Qh, g_Ql, E_);
    else if (z == 1)
        gemm_body<2>(g_xh[1], g_xl[1], g_w[1], E_, E_, m0, n0, E_ / BK,
                     QK_SCALE, nullptr, g_Kh, nullptr, E_);
    else
        gemm_body<2>(g_xh[2], g_xl[2], g_w[2], E_, E_, m0, n0, E_ / BK,
                     1.0f, nullptr, g_Vh, nullptr, E_);
}

__global__ void __launch_bounds__(TB, 1)
scores_kernel()
{
    if ((int)blockIdx.x > (int)blockIdx.y) return;   // fully above causal diagonal
    const int b = blockIdx.z;
    const size_t qo = (size_t)b * T_ * E_;
    gemm_body<0>(g_Qh + qo, g_Ql + qo, g_Kh + qo, E_, E_,
                 blockIdx.y * BM, blockIdx.x * BN, E_ / BK, 1.0f,
                 g_S + (size_t)b * T_ * T_, nullptr, nullptr, T_);
}

__global__ void __launch_bounds__(TB, 1)
out_kernel(float* __restrict__ out)
{
    const int b = blockIdx.z;
    const int m0 = blockIdx.y * BM;
    const int kT = (m0 + BM) / BK;   // causal clamp: P cols beyond m0+127 are zero
    gemm_body<0>(g_Ph + (size_t)b * T_ * T_, g_Pl + (size_t)b * T_ * T_,
                 g_Vt + (size_t)b * E_ * T_,
                 T_, T_, m0, blockIdx.x * BN, kT, 1.0f,
                 out + (size_t)b * T_ * E_, nullptr, nullptr, E_);
}

__global__ void __launch_bounds__(256)
convert_split_kernel(const float* __restrict__ in, __half* __restrict__ hi,
                     __half* __restrict__ lo, int n4)
{
    int i = blockIdx.x * blockDim.x + threadIdx.x;
    const int stride = gridDim.x * blockDim.x;
    for (; i < n4; i += stride) {
        float4 x = ((const float4*)in)[i];
        __half h0 = __float2half(x.x), h1 = __float2half(x.y);
        __half h2 = __float2half(x.z), h3 = __float2half(x.w);
        __half2 hh0; hh0.x = h0; hh0.y = h1;
        __half2 hh1; hh1.x = h2; hh1.y = h3;
        __half2 ll0, ll1;
        ll0.x = __float2half(x.x - __half2float(h0));
        ll0.y = __float2half(x.y - __half2float(h1));
        ll1.x = __float2half(x.z - __half2float(h2));
        ll1.y = __float2half(x.w - __half2float(h3));
        ((__half2*)hi)[2 * i] = hh0;
        ((__half2*)hi)[2 * i + 1] = hh1;
        ((__half2*)lo)[2 * i] = ll0;
        ((__half2*)lo)[2 * i + 1] = ll1;
    }
}

__global__ void __launch_bounds__(256)
convert_w_kernel(const float* __restrict__ in, __half* __restrict__ out, int n4)
{
    int i = blockIdx.x * blockDim.x + threadIdx.x;
    const int stride = gridDim.x * blockDim.x;
    for (; i < n4; i += stride) {
        float4 x = ((const float4*)in)[i];
        __half2 h0; h0.x = __float2half(x.x); h0.y = __float2half(x.y);
        __half2 h1; h1.x = __float2half(x.z); h1.y = __float2half(x.w);
        ((__half2*)out)[2 * i] = h0;
        ((__half2*)out)[2 * i + 1] = h1;
    }
}

__global__ void __launch_bounds__(256)
transpose_v_kernel()
{
    __shared__ float tile[32][33];
    const int b = blockIdx.z;
    const int e0 = blockIdx.x * 32;
    const int t0 = blockIdx.y * 32;
    const int tx = threadIdx.x & 31;
    const int ty = threadIdx.x >> 5;
    const __half* src = g_Vh + (size_t)b * T_ * E_;
#pragma unroll
    for (int k = 0; k < 4; ++k) {
        int i = ty + k * 8;
        tile[i][tx] = __half2float(src[(size_t)(t0 + i) * E_ + e0 + tx]);
    }
    __syncthreads();
    __half* dst = g_Vt + (size_t)b * E_ * T_;
#pragma unroll
    for (int k = 0; k < 4; ++k) {
        int i = ty + k * 8;
        dst[(size_t)(e0 + i) * T_ + t0 + tx] = __float2half(tile[tx][i]);
    }
}

__global__ void __launch_bounds__(256)
softmax_kernel()
{
    const int i = blockIdx.x;
    const int b = blockIdx.y;
    float* row = g_S + ((size_t)b * T_ + i) * T_;
    __half* ph = g_Ph + ((size_t)b * T_ + i) * T_;
    __half* pl = g_Pl + ((size_t)b * T_ + i) * T_;
    const int L = i + 1;
    const int tid = threadIdx.x;
    __shared__ float red[8];

    float m = -3.4e38f;
    for (int j = tid; j < L; j += 256) m = fmaxf(m, row[j]);
#pragma unroll
    for (int o = 16; o > 0; o >>= 1) m = fmaxf(m, __shfl_xor_sync(0xffffffffu, m, o));
    if ((tid & 31) == 0) red[tid >> 5] = m;
    __syncthreads();
    if (tid == 0) {
        float mm = red[0];
#pragma unroll
        for (int w = 1; w < 8; ++w) mm = fmaxf(mm, red[w]);
        red[0] = mm;
    }
    __syncthreads();
    m = red[0];
    __syncthreads();

    float s = 0.0f;
    for (int j = tid; j < L; j += 256) {
        float e = __expf(row[j] - m);
        row[j] = e;
        s += e;
    }
#pragma unroll
    for (int o = 16; o > 0; o >>= 1) s += __shfl_xor_sync(0xffffffffu, s, o);
    if ((tid & 31) == 0) red[tid >> 5] = s;
    __syncthreads();
    if (tid == 0) {
        float ss = 0.0f;
#pragma unroll
        for (int w = 0; w < 8; ++w) ss += red[w];
        red[0] = ss;
    }
    __syncthreads();
    const float inv = 1.0f / red[0];

    for (int j = tid; j < T_; j += 256) {
        if (j < L) {
            float p = row[j] * inv;
            __half h = __float2half(p);
            ph[j] = h;
            pl[j] = __float2half(p - __half2float(h));
        } else {
            ph[j] = __float2half(0.0f);
            pl[j] = __float2half(0.0f);
        }
    }
}

// ---------------- launch ----------------
extern "C" void kernel_launch(void* const* d_in, const int* in_sizes, int n_in,
                              void* d_out, int out_size)
{
    const float* q  = (const float*)d_in[0];
    const float* k  = (const float*)d_in[1];
    const float* v  = (const float*)d_in[2];
    const float* Wq = (const float*)d_in[3];
    const float* Wk = (const float*)d_in[4];
    const float* Wv = (const float*)d_in[5];
    float* out = (float*)d_out;

    cudaFuncSetAttribute(proj_kernel,   cudaFuncAttributeMaxDynamicSharedMemorySize, DSMEM);
    cudaFuncSetAttribute(scores_kernel, cudaFuncAttributeMaxDynamicSharedMemorySize, DSMEM);
    cudaFuncSetAttribute(out_kernel,    cudaFuncAttributeMaxDynamicSharedMemorySize, DSMEM);

    __half *xh0, *xl0, *w0;
    cudaGetSymbolAddress((void**)&xh0, g_xh);
    cudaGetSymbolAddress((void**)&xl0, g_xl);
    cudaGetSymbolAddress((void**)&w0, g_w);
    __half *xh1 = xh0 + (size_t)M_ * E_, *xh2 = xh1 + (size_t)M_ * E_;
    __half *xl1 = xl0 + (size_t)M_ * E_, *xl2 = xl1 + (size_t)M_ * E_;
    __half *w1 = w0 + (size_t)E_ * E_, *w2 = w1 + (size_t)E_ * E_;

    const int n4x = M_ * E_ / 4;
    const int n4w = E_ * E_ / 4;
    convert_split_kernel<<<2048, 256>>>(q, xh0, xl0, n4x);
    convert_split_kernel<<<2048, 256>>>(k, xh1, xl1, n4x);
    convert_split_kernel<<<2048, 256>>>(v, xh2, xl2, n4x);
    convert_w_kernel<<<512, 256>>>(Wq, w0, n4w);
    convert_w_kernel<<<512, 256>>>(Wk, w1, n4w);
    convert_w_kernel<<<512, 256>>>(Wv, w2, n4w);

    proj_kernel<<<dim3(E_ / BN, M_ / BM, 3), TB, DSMEM>>>();
    transpose_v_kernel<<<dim3(E_ / 32, T_ / 32, B_), 256>>>();
    scores_kernel<<<dim3(T_ / BN, T_ / BM, B_), TB, DSMEM>>>();
    softmax_kernel<<<dim3(T_, B_), 256>>>();
    out_kernel<<<dim3(E_ / BN, T_ / BM, B_), TB, DSMEM>>>(out);
}

// round 6
// speedup vs baseline: 7.0043x; 1.6082x over previous
#include <cuda_runtime.h>
#include <cuda_fp16.h>

#define B_ 8
#define T_ 2048
#define E_ 1024
#define M_ (B_ * T_)

#define BM 128
#define BN 128
#define BK 64
#define TB 256
#define NSTAGE 4
#define SUBT 16384u                      // one 128x64 fp16 subtile
#define STAGE_BYTES (2 * SUBT)           // A, B
#define DSMEM (NSTAGE * STAGE_BYTES)     // 131072
#define QK_SCALE 0.17677669529663687f    // 1024^-0.25

// ---------------- scratch ----------------
__device__ __half g_x[3][(size_t)M_ * E_];
__device__ __half g_w[3][(size_t)E_ * E_];
__device__ __half g_Q[(size_t)M_ * E_];
__device__ __half g_K[(size_t)M_ * E_];
__device__ __half g_V[(size_t)M_ * E_];
__device__ __half g_Vt[(size_t)B_ * E_ * T_];
__device__ float  g_S[(size_t)B_ * T_ * T_];
__device__ __half g_P[(size_t)B_ * T_ * T_];

// ---------------- helpers ----------------
__device__ __forceinline__ unsigned smem_u32(const void* p) {
    return (unsigned)__cvta_generic_to_shared(p);
}
// 128B rows, 8x16B chunks, SW128 xor swizzle: conflict-free for ldmatrix
__device__ __forceinline__ unsigned swz128(int r, int c) {
    return (unsigned)(r * 128 + ((c ^ (r & 7)) * 16));
}
__device__ __forceinline__ void cp_async16(unsigned s, const void* g) {
    asm volatile("cp.async.cg.shared.global [%0], [%1], 16;" :: "r"(s), "l"(g) : "memory");
}
__device__ __forceinline__ void ldsm4(unsigned* r, unsigned addr) {
    asm volatile("ldmatrix.sync.aligned.m8n8.x4.shared.b16 {%0,%1,%2,%3}, [%4];"
                 : "=r"(r[0]), "=r"(r[1]), "=r"(r[2]), "=r"(r[3]) : "r"(addr));
}
__device__ __forceinline__ void mma16816(float* c, const unsigned* a, unsigned b0, unsigned b1) {
    asm volatile(
        "mma.sync.aligned.m16n8k16.row.col.f32.f16.f16.f32 "
        "{%0,%1,%2,%3}, {%4,%5,%6,%7}, {%8,%9}, {%0,%1,%2,%3};"
        : "+f"(c[0]), "+f"(c[1]), "+f"(c[2]), "+f"(c[3])
        : "r"(a[0]), "r"(a[1]), "r"(a[2]), "r"(a[3]), "r"(b0), "r"(b1));
}

// ---------------- single-pass fp16 mma.sync GEMM body ----------------
// D[m0..+128, n0..+128] = A * B^T (both fp16, K-major)
// EPI 0: fp32 to Cf ; EPI 2: scale + fp16 to Ch
template <int EPI>
__device__ __forceinline__ void gemm_body(
    const __half* __restrict__ A, const __half* __restrict__ Bs,
    int lda, int ldb, int m0, int n0, int kTiles, float scale,
    float* __restrict__ Cf, __half* __restrict__ Ch, int ldc)
{
    extern __shared__ __align__(128) char smem[];
    const unsigned sbase = smem_u32(smem);
    const int tid = threadIdx.x;
    const int wid = tid >> 5;
    const int lane = tid & 31;
    const int wm = wid & 1;        // 2 m-tiles of 64
    const int wn = wid >> 1;       // 4 n-tiles of 32

    // ldmatrix offsets within a subtile
    unsigned aoff[4][4], boff[2][4];
#pragma unroll
    for (int mi = 0; mi < 4; ++mi)
#pragma unroll
        for (int ks = 0; ks < 4; ++ks)
            aoff[mi][ks] = swz128(wm * 64 + mi * 16 + (lane & 15), ks * 2 + (lane >> 4));
#pragma unroll
    for (int jp = 0; jp < 2; ++jp)
#pragma unroll
        for (int ks = 0; ks < 4; ++ks)
            boff[jp][ks] = swz128(wn * 32 + jp * 16 + ((lane >> 4) & 1) * 8 + (lane & 7),
                                  ks * 2 + ((lane >> 3) & 1));

    float acc[4][4][4];
#pragma unroll
    for (int i = 0; i < 4; ++i)
#pragma unroll
        for (int j = 0; j < 4; ++j)
#pragma unroll
            for (int e = 0; e < 4; ++e) acc[i][j][e] = 0.0f;

    const int cc = tid & 7;        // chunk within row
    const int rr = tid >> 3;       // base row (0..31)

    auto load_stage = [&](int k0, int buf) {
        const unsigned sb = sbase + buf * STAGE_BYTES;
#pragma unroll
        for (int j = 0; j < 8; ++j) {
            const int s = j >> 2;                 // 0:A 1:B
            const int r = rr + (j & 3) * 32;
            const __half* src = (s == 0) ? A : Bs;
            const int rowbase = (s == 0) ? m0 : n0;
            const int ld = (s == 0) ? lda : ldb;
            cp_async16(sb + s * SUBT + swz128(r, cc),
                       src + (size_t)(rowbase + r) * ld + k0 + cc * 8);
        }
    };

    auto compute_ks = [&](unsigned sb, int ks) {
        unsigned a[4][4], b[2][4];
#pragma unroll
        for (int mi = 0; mi < 4; ++mi) ldsm4(a[mi], sb + aoff[mi][ks]);
#pragma unroll
        for (int jp = 0; jp < 2; ++jp) ldsm4(b[jp], sb + SUBT + boff[jp][ks]);
#pragma unroll
        for (int mi = 0; mi < 4; ++mi)
#pragma unroll
            for (int ni = 0; ni < 4; ++ni)
                mma16816(acc[mi][ni], a[mi],
                         b[ni >> 1][(ni & 1) * 2], b[ni >> 1][(ni & 1) * 2 + 1]);
    };

    // prologue: 3 commit groups (possibly empty) so group counting is uniform
    load_stage(0, 0);
    asm volatile("cp.async.commit_group;" ::: "memory");
    if (kTiles > 1) load_stage(BK, 1);
    asm volatile("cp.async.commit_group;" ::: "memory");
    if (kTiles > 2) load_stage(2 * BK, 2);
    asm volatile("cp.async.commit_group;" ::: "memory");

    for (int it = 0; it < kTiles; ++it) {
        asm volatile("cp.async.wait_group 2;" ::: "memory");
        __syncthreads();
        const unsigned sb = sbase + (it % NSTAGE) * STAGE_BYTES;
        compute_ks(sb, 0);
        if (it + 3 < kTiles) load_stage((it + 3) * BK, (it + 3) % NSTAGE);
        asm volatile("cp.async.commit_group;" ::: "memory");
        compute_ks(sb, 1);
        compute_ks(sb, 2);
        compute_ks(sb, 3);
    }

    // epilogue
    const int g = lane >> 2, tig = lane & 3;
#pragma unroll
    for (int mi = 0; mi < 4; ++mi) {
#pragma unroll
        for (int ni = 0; ni < 4; ++ni) {
            const int row = m0 + wm * 64 + mi * 16 + g;
            const int col = n0 + wn * 32 + ni * 8 + tig * 2;
#pragma unroll
            for (int h = 0; h < 2; ++h) {
                const int r = row + h * 8;
                float v0 = acc[mi][ni][2 * h + 0];
                float v1 = acc[mi][ni][2 * h + 1];
                if (EPI == 0) {
                    *(float2*)(Cf + (size_t)r * ldc + col) = make_float2(v0, v1);
                } else {
                    __half2 hh;
                    hh.x = __float2half(v0 * scale);
                    hh.y = __float2half(v1 * scale);
                    *(__half2*)(Ch + (size_t)r * ldc + col) = hh;
                }
            }
        }
    }
}

// ---------------- kernels ----------------
__global__ void __launch_bounds__(TB, 1)
proj_kernel()
{
    const int z = blockIdx.z;
    const int m0 = blockIdx.y * BM;
    const int n0 = blockIdx.x * BN;
    __half* dst = (z == 0) ? g_Q : (z == 1) ? g_K : g_V;
    const float scale = (z < 2) ? QK_SCALE : 1.0f;
    gemm_body<2>(g_x[z], g_w[z], E_, E_, m0, n0, E_ / BK, scale, nullptr, dst, E_);
}

__global__ void __launch_bounds__(TB, 1)
scores_kernel()
{
    if ((int)blockIdx.x > (int)blockIdx.y) return;   // fully above causal diagonal
    const int b = blockIdx.z;
    const size_t qo = (size_t)b * T_ * E_;
    gemm_body<0>(g_Q + qo, g_K + qo, E_, E_,
                 blockIdx.y * BM, blockIdx.x * BN, E_ / BK, 1.0f,
                 g_S + (size_t)b * T_ * T_, nullptr, T_);
}

__global__ void __launch_bounds__(TB, 1)
out_kernel(float* __restrict__ out)
{
    const int b = blockIdx.z;
    const int m0 = blockIdx.y * BM;
    const int kT = (m0 + BM) / BK;   // causal clamp: P cols beyond m0+127 are zero
    gemm_body<0>(g_P + (size_t)b * T_ * T_, g_Vt + (size_t)b * E_ * T_,
                 T_, T_, m0, blockIdx.x * BN, kT, 1.0f,
                 out + (size_t)b * T_ * E_, nullptr, E_);
}

__global__ void __launch_bounds__(256)
convert_kernel(const float* __restrict__ in, __half* __restrict__ out, int n4)
{
    int i = blockIdx.x * blockDim.x + threadIdx.x;
    const int stride = gridDim.x * blockDim.x;
    for (; i < n4; i += stride) {
        float4 x = ((const float4*)in)[i];
        __half2 h0; h0.x = __float2half(x.x); h0.y = __float2half(x.y);
        __half2 h1; h1.x = __float2half(x.z); h1.y = __float2half(x.w);
        ((__half2*)out)[2 * i] = h0;
        ((__half2*)out)[2 * i + 1] = h1;
    }
}

__global__ void __launch_bounds__(256)
transpose_v_kernel()
{
    __shared__ __half tile[32][36];
    const int b = blockIdx.z;
    const int e0 = blockIdx.x * 32;
    const int t0 = blockIdx.y * 32;
    const int tx = threadIdx.x & 31;
    const int ty = threadIdx.x >> 5;
    const __half* src = g_V + (size_t)b * T_ * E_;
#pragma unroll
    for (int k = 0; k < 4; ++k) {
        int i = ty + k * 8;
        tile[i][tx] = src[(size_t)(t0 + i) * E_ + e0 + tx];
    }
    __syncthreads();
    __half* dst = g_Vt + (size_t)b * E_ * T_;
#pragma unroll
    for (int k = 0; k < 4; ++k) {
        int i = ty + k * 8;
        dst[(size_t)(e0 + i) * T_ + t0 + tx] = tile[tx][i];
    }
}

__global__ void __launch_bounds__(256)
softmax_kernel()
{
    const int i = blockIdx.x;
    const int b = blockIdx.y;
    float* row = g_S + ((size_t)b * T_ + i) * T_;
    __half* ph = g_P + ((size_t)b * T_ + i) * T_;
    const int L = i + 1;
    const int tid = threadIdx.x;
    __shared__ float red[8];

    float m = -3.4e38f;
    for (int j = tid; j < L; j += 256) m = fmaxf(m, row[j]);
#pragma unroll
    for (int o = 16; o > 0; o >>= 1) m = fmaxf(m, __shfl_xor_sync(0xffffffffu, m, o));
    if ((tid & 31) == 0) red[tid >> 5] = m;
    __syncthreads();
    if (tid == 0) {
        float mm = red[0];
#pragma unroll
        for (int w = 1; w < 8; ++w) mm = fmaxf(mm, red[w]);
        red[0] = mm;
    }
    __syncthreads();
    m = red[0];
    __syncthreads();

    float s = 0.0f;
    for (int j = tid; j < L; j += 256) {
        float e = __expf(row[j] - m);
        row[j] = e;
        s += e;
    }
#pragma unroll
    for (int o = 16; o > 0; o >>= 1) s += __shfl_xor_sync(0xffffffffu, s, o);
    if ((tid & 31) == 0) red[tid >> 5] = s;
    __syncthreads();
    if (tid == 0) {
        float ss = 0.0f;
#pragma unroll
        for (int w = 0; w < 8; ++w) ss += red[w];
        red[0] = ss;
    }
    __syncthreads();
    const float inv = 1.0f / red[0];

    for (int j = tid; j < T_; j += 256) {
        if (j < L) ph[j] = __float2half(row[j] * inv);
        else       ph[j] = __float2half(0.0f);
    }
}

// ---------------- launch ----------------
extern "C" void kernel_launch(void* const* d_in, const int* in_sizes, int n_in,
                              void* d_out, int out_size)
{
    const float* q  = (const float*)d_in[0];
    const float* k  = (const float*)d_in[1];
    const float* v  = (const float*)d_in[2];
    const float* Wq = (const float*)d_in[3];
    const float* Wk = (const float*)d_in[4];
    const float* Wv = (const float*)d_in[5];
    float* out = (float*)d_out;

    cudaFuncSetAttribute(proj_kernel,   cudaFuncAttributeMaxDynamicSharedMemorySize, DSMEM);
    cudaFuncSetAttribute(scores_kernel, cudaFuncAttributeMaxDynamicSharedMemorySize, DSMEM);
    cudaFuncSetAttribute(out_kernel,    cudaFuncAttributeMaxDynamicSharedMemorySize, DSMEM);

    __half *x0, *w0;
    cudaGetSymbolAddress((void**)&x0, g_x);
    cudaGetSymbolAddress((void**)&w0, g_w);
    __half *x1 = x0 + (size_t)M_ * E_, *x2 = x1 + (size_t)M_ * E_;
    __half *w1 = w0 + (size_t)E_ * E_, *w2 = w1 + (size_t)E_ * E_;

    const int n4x = M_ * E_ / 4;
    const int n4w = E_ * E_ / 4;
    convert_kernel<<<2048, 256>>>(q, x0, n4x);
    convert_kernel<<<2048, 256>>>(k, x1, n4x);
    convert_kernel<<<2048, 256>>>(v, x2, n4x);
    convert_kernel<<<512, 256>>>(Wq, w0, n4w);
    convert_kernel<<<512, 256>>>(Wk, w1, n4w);
    convert_kernel<<<512, 256>>>(Wv, w2, n4w);

    proj_kernel<<<dim3(E_ / BN, M_ / BM, 3), TB, DSMEM>>>();
    transpose_v_kernel<<<dim3(E_ / 32, T_ / 32, B_), 256>>>();
    scores_kernel<<<dim3(T_ / BN, T_ / BM, B_), TB, DSMEM>>>();
    softmax_kernel<<<dim3(T_, B_), 256>>>();
    out_kernel<<<dim3(E_ / BN, T_ / BM, B_), TB, DSMEM>>>(out);
}

// round 7
// speedup vs baseline: 7.4125x; 1.0583x over previous
#include <cuda_runtime.h>
#include <cuda_fp16.h>

#define B_ 8
#define T_ 2048
#define E_ 1024
#define M_ (B_ * T_)

#define BM 128
#define BN 256
#define BK 64
#define TB 256
#define NSTAGE 3
#define ASUB 16384u                      // 128x64 fp16
#define BSUB 32768u                      // 256x64 fp16
#define STAGE_BYTES (ASUB + BSUB)        // 49152
#define DSMEM (NSTAGE * STAGE_BYTES)     // 147456
#define QK_SCALE 0.17677669529663687f    // 1024^-0.25

// ---------------- scratch ----------------
__device__ __half g_x[3][(size_t)M_ * E_];
__device__ __half g_w[3][(size_t)E_ * E_];
__device__ __half g_Q[(size_t)M_ * E_];
__device__ __half g_K[(size_t)M_ * E_];
__device__ __half g_V[(size_t)M_ * E_];
__device__ __half g_Vt[(size_t)B_ * E_ * T_];
__device__ float  g_S[(size_t)B_ * T_ * T_];
__device__ __half g_P[(size_t)B_ * T_ * T_];

// ---------------- helpers ----------------
__device__ __forceinline__ unsigned smem_u32(const void* p) {
    return (unsigned)__cvta_generic_to_shared(p);
}
// 128B rows, 8x16B chunks, SW128 xor swizzle: conflict-free for ldmatrix
__device__ __forceinline__ unsigned swz128(int r, int c) {
    return (unsigned)(r * 128 + ((c ^ (r & 7)) * 16));
}
__device__ __forceinline__ void cp_async16(unsigned s, const void* g) {
    asm volatile("cp.async.cg.shared.global [%0], [%1], 16;" :: "r"(s), "l"(g) : "memory");
}
__device__ __forceinline__ void ldsm4(unsigned* r, unsigned addr) {
    asm volatile("ldmatrix.sync.aligned.m8n8.x4.shared.b16 {%0,%1,%2,%3}, [%4];"
                 : "=r"(r[0]), "=r"(r[1]), "=r"(r[2]), "=r"(r[3]) : "r"(addr));
}
__device__ __forceinline__ void mma16816(float* c, const unsigned* a, unsigned b0, unsigned b1) {
    asm volatile(
        "mma.sync.aligned.m16n8k16.row.col.f32.f16.f16.f32 "
        "{%0,%1,%2,%3}, {%4,%5,%6,%7}, {%8,%9}, {%0,%1,%2,%3};"
        : "+f"(c[0]), "+f"(c[1]), "+f"(c[2]), "+f"(c[3])
        : "r"(a[0]), "r"(a[1]), "r"(a[2]), "r"(a[3]), "r"(b0), "r"(b1));
}

// ---------------- single-pass fp16 mma.sync GEMM body (128x256 tile) --------
// D[m0..+128, n0..+256] = A * B^T (both fp16, K-major)
// Warp tile 64x64. EPI 0: fp32 to Cf ; EPI 2: scale + fp16 to Ch
template <int EPI>
__device__ __forceinline__ void gemm_body(
    const __half* __restrict__ A, const __half* __restrict__ Bs,
    int lda, int ldb, int m0, int n0, int kTiles, float scale,
    float* __restrict__ Cf, __half* __restrict__ Ch, int ldc)
{
    extern __shared__ __align__(128) char smem[];
    const unsigned sbase = smem_u32(smem);
    const int tid = threadIdx.x;
    const int wid = tid >> 5;
    const int lane = tid & 31;
    const int wm = wid & 1;        // 2 m-tiles of 64
    const int wn = wid >> 1;       // 4 n-tiles of 64

    // ldmatrix offsets within a subtile
    unsigned aoff[4][4], boff[4][4];
#pragma unroll
    for (int mi = 0; mi < 4; ++mi)
#pragma unroll
        for (int ks = 0; ks < 4; ++ks)
            aoff[mi][ks] = swz128(wm * 64 + mi * 16 + (lane & 15), ks * 2 + (lane >> 4));
#pragma unroll
    for (int jp = 0; jp < 4; ++jp)
#pragma unroll
        for (int ks = 0; ks < 4; ++ks)
            boff[jp][ks] = swz128(wn * 64 + jp * 16 + ((lane >> 4) & 1) * 8 + (lane & 7),
                                  ks * 2 + ((lane >> 3) & 1));

    float acc[4][8][4];
#pragma unroll
    for (int i = 0; i < 4; ++i)
#pragma unroll
        for (int j = 0; j < 8; ++j)
#pragma unroll
            for (int e = 0; e < 4; ++e) acc[i][j][e] = 0.0f;

    const int cc = tid & 7;        // chunk within row
    const int rr = tid >> 3;       // base row (0..31)

    auto load_stage = [&](int k0, int buf) {
        const unsigned sb = sbase + buf * STAGE_BYTES;
#pragma unroll
        for (int j = 0; j < 4; ++j) {          // A: 128 rows
            const int r = rr + j * 32;
            cp_async16(sb + swz128(r, cc),
                       A + (size_t)(m0 + r) * lda + k0 + cc * 8);
        }
#pragma unroll
        for (int j = 0; j < 8; ++j) {          // B: 256 rows
            const int r = rr + j * 32;
            cp_async16(sb + ASUB + swz128(r, cc),
                       Bs + (size_t)(n0 + r) * ldb + k0 + cc * 8);
        }
    };

    auto compute_ks = [&](unsigned sb, int ks) {
        unsigned a[4][4], b[4][4];
#pragma unroll
        for (int mi = 0; mi < 4; ++mi) ldsm4(a[mi], sb + aoff[mi][ks]);
#pragma unroll
        for (int jp = 0; jp < 4; ++jp) ldsm4(b[jp], sb + ASUB + boff[jp][ks]);
#pragma unroll
        for (int mi = 0; mi < 4; ++mi)
#pragma unroll
            for (int ni = 0; ni < 8; ++ni)
                mma16816(acc[mi][ni], a[mi],
                         b[ni >> 1][(ni & 1) * 2], b[ni >> 1][(ni & 1) * 2 + 1]);
    };

    load_stage(0, 0);
    asm volatile("cp.async.commit_group;" ::: "memory");
    if (kTiles > 1) load_stage(BK, 1);
    asm volatile("cp.async.commit_group;" ::: "memory");

    for (int it = 0; it < kTiles; ++it) {
        asm volatile("cp.async.wait_group 1;" ::: "memory");
        __syncthreads();
        const unsigned sb = sbase + (it % NSTAGE) * STAGE_BYTES;
        compute_ks(sb, 0);
        if (it + 2 < kTiles) load_stage((it + 2) * BK, (it + 2) % NSTAGE);
        asm volatile("cp.async.commit_group;" ::: "memory");
        compute_ks(sb, 1);
        compute_ks(sb, 2);
        compute_ks(sb, 3);
    }

    // epilogue
    const int g = lane >> 2, tig = lane & 3;
#pragma unroll
    for (int mi = 0; mi < 4; ++mi) {
#pragma unroll
        for (int ni = 0; ni < 8; ++ni) {
            const int row = m0 + wm * 64 + mi * 16 + g;
            const int col = n0 + wn * 64 + ni * 8 + tig * 2;
#pragma unroll
            for (int h = 0; h < 2; ++h) {
                const int r = row + h * 8;
                float v0 = acc[mi][ni][2 * h + 0];
                float v1 = acc[mi][ni][2 * h + 1];
                if (EPI == 0) {
                    *(float2*)(Cf + (size_t)r * ldc + col) = make_float2(v0, v1);
                } else {
                    __half2 hh;
                    hh.x = __float2half(v0 * scale);
                    hh.y = __float2half(v1 * scale);
                    *(__half2*)(Ch + (size_t)r * ldc + col) = hh;
                }
            }
        }
    }
}

// ---------------- kernels ----------------
__global__ void __launch_bounds__(TB, 1)
proj_kernel()
{
    const int z = blockIdx.z;
    const int m0 = blockIdx.y * BM;
    const int n0 = blockIdx.x * BN;
    __half* dst = (z == 0) ? g_Q : (z == 1) ? g_K : g_V;
    const float scale = (z < 2) ? QK_SCALE : 1.0f;
    gemm_body<2>(g_x[z], g_w[z], E_, E_, m0, n0, E_ / BK, scale, nullptr, dst, E_);
}

__global__ void __launch_bounds__(TB, 1)
scores_kernel()
{
    // skip blocks entirely above the causal diagonal: n0 > m0+127  <=>  2bx > by
    if (2 * (int)blockIdx.x > (int)blockIdx.y) return;
    const int b = blockIdx.z;
    const size_t qo = (size_t)b * T_ * E_;
    gemm_body<0>(g_Q + qo, g_K + qo, E_, E_,
                 blockIdx.y * BM, blockIdx.x * BN, E_ / BK, 1.0f,
                 g_S + (size_t)b * T_ * T_, nullptr, T_);
}

__global__ void __launch_bounds__(TB, 1)
out_kernel(float* __restrict__ out)
{
    const int b = blockIdx.z;
    const int m0 = blockIdx.y * BM;
    const int kT = (m0 + BM) / BK;   // causal clamp: P cols beyond m0+127 are zero
    gemm_body<0>(g_P + (size_t)b * T_ * T_, g_Vt + (size_t)b * E_ * T_,
                 T_, T_, m0, blockIdx.x * BN, kT, 1.0f,
                 out + (size_t)b * T_ * E_, nullptr, E_);
}

__global__ void __launch_bounds__(256)
convert3_kernel(const float* __restrict__ a, const float* __restrict__ b,
                const float* __restrict__ c, __half* __restrict__ o0,
                __half* __restrict__ o1, __half* __restrict__ o2, int n4)
{
    const float* in = (blockIdx.z == 0) ? a : (blockIdx.z == 1) ? b : c;
    __half* out = (blockIdx.z == 0) ? o0 : (blockIdx.z == 1) ? o1 : o2;
    int i = blockIdx.x * blockDim.x + threadIdx.x;
    const int stride = gridDim.x * blockDim.x;
    for (; i < n4; i += stride) {
        float4 x = ((const float4*)in)[i];
        __half2 h0; h0.x = __float2half(x.x); h0.y = __float2half(x.y);
        __half2 h1; h1.x = __float2half(x.z); h1.y = __float2half(x.w);
        ((__half2*)out)[2 * i] = h0;
        ((__half2*)out)[2 * i + 1] = h1;
    }
}

__global__ void __launch_bounds__(256)
transpose_v_kernel()
{
    __shared__ __half tile[32][36];
    const int b = blockIdx.z;
    const int e0 = blockIdx.x * 32;
    const int t0 = blockIdx.y * 32;
    const int tx = threadIdx.x & 31;
    const int ty = threadIdx.x >> 5;
    const __half* src = g_V + (size_t)b * T_ * E_;
#pragma unroll
    for (int k = 0; k < 4; ++k) {
        int i = ty + k * 8;
        tile[i][tx] = src[(size_t)(t0 + i) * E_ + e0 + tx];
    }
    __syncthreads();
    __half* dst = g_Vt + (size_t)b * E_ * T_;
#pragma unroll
    for (int k = 0; k < 4; ++k) {
        int i = ty + k * 8;
        dst[(size_t)(e0 + i) * T_ + t0 + tx] = tile[tx][i];
    }
}

__global__ void __launch_bounds__(256)
softmax_kernel()
{
    const int i = blockIdx.x;
    const int b = blockIdx.y;
    float* row = g_S + ((size_t)b * T_ + i) * T_;
    __half* ph = g_P + ((size_t)b * T_ + i) * T_;
    const int L = i + 1;
    const int tid = threadIdx.x;
    __shared__ float red[8];

    float m = -3.4e38f;
    for (int j = tid; j < L; j += 256) m = fmaxf(m, row[j]);
#pragma unroll
    for (int o = 16; o > 0; o >>= 1) m = fmaxf(m, __shfl_xor_sync(0xffffffffu, m, o));
    if ((tid & 31) == 0) red[tid >> 5] = m;
    __syncthreads();
    if (tid == 0) {
        float mm = red[0];
#pragma unroll
        for (int w = 1; w < 8; ++w) mm = fmaxf(mm, red[w]);
        red[0] = mm;
    }
    __syncthreads();
    m = red[0];
    __syncthreads();

    float s = 0.0f;
    for (int j = tid; j < L; j += 256) {
        float e = __expf(row[j] - m);
        row[j] = e;
        s += e;
    }
#pragma unroll
    for (int o = 16; o > 0; o >>= 1) s += __shfl_xor_sync(0xffffffffu, s, o);
    if ((tid & 31) == 0) red[tid >> 5] = s;
    __syncthreads();
    if (tid == 0) {
        float ss = 0.0f;
#pragma unroll
        for (int w = 0; w < 8; ++w) ss += red[w];
        red[0] = ss;
    }
    __syncthreads();
    const float inv = 1.0f / red[0];

    for (int j = tid; j < T_; j += 256) {
        if (j < L) ph[j] = __float2half(row[j] * inv);
        else       ph[j] = __float2half(0.0f);
    }
}

// ---------------- launch ----------------
extern "C" void kernel_launch(void* const* d_in, const int* in_sizes, int n_in,
                              void* d_out, int out_size)
{
    const float* q  = (const float*)d_in[0];
    const float* k  = (const float*)d_in[1];
    const float* v  = (const float*)d_in[2];
    const float* Wq = (const float*)d_in[3];
    const float* Wk = (const float*)d_in[4];
    const float* Wv = (const float*)d_in[5];
    float* out = (float*)d_out;

    cudaFuncSetAttribute(proj_kernel,   cudaFuncAttributeMaxDynamicSharedMemorySize, DSMEM);
    cudaFuncSetAttribute(scores_kernel, cudaFuncAttributeMaxDynamicSharedMemorySize, DSMEM);
    cudaFuncSetAttribute(out_kernel,    cudaFuncAttributeMaxDynamicSharedMemorySize, DSMEM);

    __half *x0, *w0;
    cudaGetSymbolAddress((void**)&x0, g_x);
    cudaGetSymbolAddress((void**)&w0, g_w);
    __half *x1 = x0 + (size_t)M_ * E_, *x2 = x1 + (size_t)M_ * E_;
    __half *w1 = w0 + (size_t)E_ * E_, *w2 = w1 + (size_t)E_ * E_;

    const int n4x = M_ * E_ / 4;
    const int n4w = E_ * E_ / 4;
    convert3_kernel<<<dim3(1024, 1, 3), 256>>>(q, k, v, x0, x1, x2, n4x);
    convert3_kernel<<<dim3(256, 1, 3), 256>>>(Wq, Wk, Wv, w0, w1, w2, n4w);

    proj_kernel<<<dim3(E_ / BN, M_ / BM, 3), TB, DSMEM>>>();
    transpose_v_kernel<<<dim3(E_ / 32, T_ / 32, B_), 256>>>();
    scores_kernel<<<dim3(T_ / BN, T_ / BM, B_), TB, DSMEM>>>();
    softmax_kernel<<<dim3(T_, B_), 256>>>();
    out_kernel<<<dim3(E_ / BN, T_ / BM, B_), TB, DSMEM>>>(out);
}

// round 8
// speedup vs baseline: 8.3309x; 1.1239x over previous
#include <cuda_runtime.h>
#include <cuda_fp16.h>

#define B_ 8
#define T_ 2048
#define E_ 1024
#define M_ (B_ * T_)

#define BM 128
#define BN 128
#define BK 64
#define TB 256
#define NSTAGE 3
#define ASUB 16384u                      // 128x64 fp16
#define STAGE_BYTES (2 * ASUB)           // 32768
#define DSMEM (NSTAGE * STAGE_BYTES)     // 98304
#define QK_SCALE 0.17677669529663687f    // 1024^-0.25

// ---------------- scratch ----------------
__device__ __half g_x[3][(size_t)M_ * E_];
__device__ __half g_w[3][(size_t)E_ * E_];
__device__ __half g_Q[(size_t)M_ * E_];
__device__ __half g_K[(size_t)M_ * E_];
__device__ __half g_V[(size_t)M_ * E_];
__device__ __half g_Vt[(size_t)B_ * E_ * T_];
__device__ float  g_S[(size_t)B_ * T_ * T_];
__device__ __half g_P[(size_t)B_ * T_ * T_];

// ---------------- helpers ----------------
__device__ __forceinline__ unsigned smem_u32(const void* p) {
    return (unsigned)__cvta_generic_to_shared(p);
}
// 128B rows, 8x16B chunks, SW128 xor swizzle: conflict-free for ldmatrix
__device__ __forceinline__ unsigned swz128(int r, int c) {
    return (unsigned)(r * 128 + ((c ^ (r & 7)) * 16));
}
__device__ __forceinline__ void cp_async16(unsigned s, const void* g) {
    asm volatile("cp.async.cg.shared.global [%0], [%1], 16;" :: "r"(s), "l"(g) : "memory");
}
__device__ __forceinline__ void ldsm4(unsigned* r, unsigned addr) {
    asm volatile("ldmatrix.sync.aligned.m8n8.x4.shared.b16 {%0,%1,%2,%3}, [%4];"
                 : "=r"(r[0]), "=r"(r[1]), "=r"(r[2]), "=r"(r[3]) : "r"(addr));
}
__device__ __forceinline__ void mma16816(float* c, const unsigned* a, unsigned b0, unsigned b1) {
    asm volatile(
        "mma.sync.aligned.m16n8k16.row.col.f32.f16.f16.f32 "
        "{%0,%1,%2,%3}, {%4,%5,%6,%7}, {%8,%9}, {%0,%1,%2,%3};"
        : "+f"(c[0]), "+f"(c[1]), "+f"(c[2]), "+f"(c[3])
        : "r"(a[0]), "r"(a[1]), "r"(a[2]), "r"(a[3]), "r"(b0), "r"(b1));
}

// ---------------- single-pass fp16 mma.sync GEMM body (128x128 tile) --------
// D[m0..+128, n0..+128] = A * B^T (both fp16, K-major). Warp tile 64x32.
// EPI 0: fp32 to Cf ; EPI 2: scale + fp16 to Ch
template <int EPI>
__device__ __forceinline__ void gemm_body(
    const __half* __restrict__ A, const __half* __restrict__ Bs,
    int lda, int ldb, int m0, int n0, int kTiles, float scale,
    float* __restrict__ Cf, __half* __restrict__ Ch, int ldc)
{
    extern __shared__ __align__(128) char smem[];
    const unsigned sbase = smem_u32(smem);
    const int tid = threadIdx.x;
    const int wid = tid >> 5;
    const int lane = tid & 31;
    const int wm = wid & 1;        // 2 m-tiles of 64
    const int wn = wid >> 1;       // 4 n-tiles of 32

    // per-ks base ldmatrix offsets; row +16 adds exactly 2048 bytes (swizzle-safe)
    unsigned abase[4], bbase[4];
#pragma unroll
    for (int ks = 0; ks < 4; ++ks) {
        abase[ks] = swz128(wm * 64 + (lane & 15), ks * 2 + (lane >> 4));
        bbase[ks] = ASUB + swz128(wn * 32 + ((lane >> 4) & 1) * 8 + (lane & 7),
                                  ks * 2 + ((lane >> 3) & 1));
    }

    float acc[4][4][4];
#pragma unroll
    for (int i = 0; i < 4; ++i)
#pragma unroll
        for (int j = 0; j < 4; ++j)
#pragma unroll
            for (int e = 0; e < 4; ++e) acc[i][j][e] = 0.0f;

    const int cc = tid & 7;        // chunk within row
    const int rr = tid >> 3;       // base row (0..31)

    auto load_stage = [&](int k0, int buf) {
        const unsigned sb = sbase + buf * STAGE_BYTES;
#pragma unroll
        for (int j = 0; j < 4; ++j) {          // A: 128 rows
            const int r = rr + j * 32;
            cp_async16(sb + swz128(r, cc),
                       A + (size_t)(m0 + r) * lda + k0 + cc * 8);
        }
#pragma unroll
        for (int j = 0; j < 4; ++j) {          // B: 128 rows
            const int r = rr + j * 32;
            cp_async16(sb + ASUB + swz128(r, cc),
                       Bs + (size_t)(n0 + r) * ldb + k0 + cc * 8);
        }
    };

    auto compute_ks = [&](unsigned sb, int ks) {
        unsigned a[4][4], b[2][4];
#pragma unroll
        for (int mi = 0; mi < 4; ++mi) ldsm4(a[mi], sb + abase[ks] + mi * 2048);
#pragma unroll
        for (int jp = 0; jp < 2; ++jp) ldsm4(b[jp], sb + bbase[ks] + jp * 2048);
#pragma unroll
        for (int mi = 0; mi < 4; ++mi)
#pragma unroll
            for (int ni = 0; ni < 4; ++ni)
                mma16816(acc[mi][ni], a[mi],
                         b[ni >> 1][(ni & 1) * 2], b[ni >> 1][(ni & 1) * 2 + 1]);
    };

    load_stage(0, 0);
    asm volatile("cp.async.commit_group;" ::: "memory");
    if (kTiles > 1) load_stage(BK, 1);
    asm volatile("cp.async.commit_group;" ::: "memory");

    for (int it = 0; it < kTiles; ++it) {
        asm volatile("cp.async.wait_group 1;" ::: "memory");
        __syncthreads();
        const unsigned sb = sbase + (it % NSTAGE) * STAGE_BYTES;
        compute_ks(sb, 0);
        if (it + 2 < kTiles) load_stage((it + 2) * BK, (it + 2) % NSTAGE);
        asm volatile("cp.async.commit_group;" ::: "memory");
        compute_ks(sb, 1);
        compute_ks(sb, 2);
        compute_ks(sb, 3);
    }

    // epilogue
    const int g = lane >> 2, tig = lane & 3;
#pragma unroll
    for (int mi = 0; mi < 4; ++mi) {
#pragma unroll
        for (int ni = 0; ni < 4; ++ni) {
            const int row = m0 + wm * 64 + mi * 16 + g;
            const int col = n0 + wn * 32 + ni * 8 + tig * 2;
#pragma unroll
            for (int h = 0; h < 2; ++h) {
                const int r = row + h * 8;
                float v0 = acc[mi][ni][2 * h + 0];
                float v1 = acc[mi][ni][2 * h + 1];
                if (EPI == 0) {
                    *(float2*)(Cf + (size_t)r * ldc + col) = make_float2(v0, v1);
                } else {
                    __half2 hh;
                    hh.x = __float2half(v0 * scale);
                    hh.y = __float2half(v1 * scale);
                    *(__half2*)(Ch + (size_t)r * ldc + col) = hh;
                }
            }
        }
    }
}

// ---------------- kernels ----------------
__global__ void __launch_bounds__(TB, 2)
proj_kernel()
{
    const int z = blockIdx.z;
    const int m0 = blockIdx.y * BM;
    const int n0 = blockIdx.x * BN;
    __half* dst = (z == 0) ? g_Q : (z == 1) ? g_K : g_V;
    const float scale = (z < 2) ? QK_SCALE : 1.0f;
    gemm_body<2>(g_x[z], g_w[z], E_, E_, m0, n0, E_ / BK, scale, nullptr, dst, E_);
}

__global__ void __launch_bounds__(TB, 2)
scores_kernel()
{
    if ((int)blockIdx.x > (int)blockIdx.y) return;   // fully above causal diagonal
    const int b = blockIdx.z;
    const size_t qo = (size_t)b * T_ * E_;
    gemm_body<0>(g_Q + qo, g_K + qo, E_, E_,
                 blockIdx.y * BM, blockIdx.x * BN, E_ / BK, 1.0f,
                 g_S + (size_t)b * T_ * T_, nullptr, T_);
}

__global__ void __launch_bounds__(TB, 2)
out_kernel(float* __restrict__ out)
{
    const int b = blockIdx.z;
    // reversed y: heaviest (largest-kT) blocks get the lowest block ids -> start first
    const int m0 = ((int)gridDim.y - 1 - (int)blockIdx.y) * BM;
    const int kT = (m0 + BM) / BK;   // causal clamp: P cols beyond m0+127 are zero
    gemm_body<0>(g_P + (size_t)b * T_ * T_, g_Vt + (size_t)b * E_ * T_,
                 T_, T_, m0, blockIdx.x * BN, kT, 1.0f,
                 out + (size_t)b * T_ * E_, nullptr, E_);
}

__global__ void __launch_bounds__(256)
convert3_kernel(const float* __restrict__ a, const float* __restrict__ b,
                const float* __restrict__ c, __half* __restrict__ o0,
                __half* __restrict__ o1, __half* __restrict__ o2, int n4)
{
    const float* in = (blockIdx.z == 0) ? a : (blockIdx.z == 1) ? b : c;
    __half* out = (blockIdx.z == 0) ? o0 : (blockIdx.z == 1) ? o1 : o2;
    int i = blockIdx.x * blockDim.x + threadIdx.x;
    const int stride = gridDim.x * blockDim.x;
    for (; i < n4; i += stride) {
        float4 x = ((const float4*)in)[i];
        __half2 h0; h0.x = __float2half(x.x); h0.y = __float2half(x.y);
        __half2 h1; h1.x = __float2half(x.z); h1.y = __float2half(x.w);
        ((__half2*)out)[2 * i] = h0;
        ((__half2*)out)[2 * i + 1] = h1;
    }
}

// 64x64 tile, half2 vectorized both sides
__global__ void __launch_bounds__(256)
transpose_v_kernel()
{
    __shared__ __half tile[64][65];
    const int b = blockIdx.z;
    const int e0 = blockIdx.x * 64;
    const int t0 = blockIdx.y * 64;
    const int tx = threadIdx.x & 31;   // half2 column index
    const int ty = threadIdx.x >> 5;   // 0..7
    const __half2* src2 = (const __half2*)(g_V + (size_t)b * T_ * E_);
#pragma unroll
    for (int k = 0; k < 8; ++k) {
        int row = ty + k * 8;                       // t offset
        __half2 v = src2[((size_t)(t0 + row) * E_ + e0) / 2 + tx];
        tile[row][2 * tx]     = v.x;
        tile[row][2 * tx + 1] = v.y;
    }
    __syncthreads();
    __half2* dst2 = (__half2*)(g_Vt + (size_t)b * E_ * T_);
#pragma unroll
    for (int k = 0; k < 8; ++k) {
        int erow = ty + k * 8;                      // e offset
        __half2 w;
        w.x = tile[2 * tx][erow];
        w.y = tile[2 * tx + 1][erow];
        dst2[((size_t)(e0 + erow) * T_ + t0) / 2 + tx] = w;
    }
}

__global__ void __launch_bounds__(256)
softmax_kernel()
{
    const int i = blockIdx.x;
    const int b = blockIdx.y;
    float* row = g_S + ((size_t)b * T_ + i) * T_;
    __half* ph = g_P + ((size_t)b * T_ + i) * T_;
    const int L = i + 1;
    const int tid = threadIdx.x;
    __shared__ float red[8];

    float m = -3.4e38f;
    for (int j = tid; j < L; j += 256) m = fmaxf(m, row[j]);
#pragma unroll
    for (int o = 16; o > 0; o >>= 1) m = fmaxf(m, __shfl_xor_sync(0xffffffffu, m, o));
    if ((tid & 31) == 0) red[tid >> 5] = m;
    __syncthreads();
    if (tid == 0) {
        float mm = red[0];
#pragma unroll
        for (int w = 1; w < 8; ++w) mm = fmaxf(mm, red[w]);
        red[0] = mm;
    }
    __syncthreads();
    m = red[0];
    __syncthreads();

    float s = 0.0f;
    for (int j = tid; j < L; j += 256) {
        float e = __expf(row[j] - m);
        row[j] = e;
        s += e;
    }
#pragma unroll
    for (int o = 16; o > 0; o >>= 1) s += __shfl_xor_sync(0xffffffffu, s, o);
    if ((tid & 31) == 0) red[tid >> 5] = s;
    __syncthreads();
    if (tid == 0) {
        float ss = 0.0f;
#pragma unroll
        for (int w = 0; w < 8; ++w) ss += red[w];
        red[0] = ss;
    }
    __syncthreads();
    const float inv = 1.0f / red[0];

    for (int j = tid; j < T_; j += 256) {
        if (j < L) ph[j] = __float2half(row[j] * inv);
        else       ph[j] = __float2half(0.0f);
    }
}

// ---------------- launch ----------------
extern "C" void kernel_launch(void* const* d_in, const int* in_sizes, int n_in,
                              void* d_out, int out_size)
{
    const float* q  = (const float*)d_in[0];
    const float* k  = (const float*)d_in[1];
    const float* v  = (const float*)d_in[2];
    const float* Wq = (const float*)d_in[3];
    const float* Wk = (const float*)d_in[4];
    const float* Wv = (const float*)d_in[5];
    float* out = (float*)d_out;

    cudaFuncSetAttribute(proj_kernel,   cudaFuncAttributeMaxDynamicSharedMemorySize, DSMEM);
    cudaFuncSetAttribute(scores_kernel, cudaFuncAttributeMaxDynamicSharedMemorySize, DSMEM);
    cudaFuncSetAttribute(out_kernel,    cudaFuncAttributeMaxDynamicSharedMemorySize, DSMEM);

    __half *x0, *w0;
    cudaGetSymbolAddress((void**)&x0, g_x);
    cudaGetSymbolAddress((void**)&w0, g_w);
    __half *x1 = x0 + (size_t)M_ * E_, *x2 = x1 + (size_t)M_ * E_;
    __half *w1 = w0 + (size_t)E_ * E_, *w2 = w1 + (size_t)E_ * E_;

    const int n4x = M_ * E_ / 4;
    const int n4w = E_ * E_ / 4;
    convert3_kernel<<<dim3(1024, 1, 3), 256>>>(q, k, v, x0, x1, x2, n4x);
    convert3_kernel<<<dim3(256, 1, 3), 256>>>(Wq, Wk, Wv, w0, w1, w2, n4w);

    proj_kernel<<<dim3(E_ / BN, M_ / BM, 3), TB, DSMEM>>>();
    transpose_v_kernel<<<dim3(E_ / 64, T_ / 64, B_), 256>>>();
    scores_kernel<<<dim3(T_ / BN, T_ / BM, B_), TB, DSMEM>>>();
    softmax_kernel<<<dim3(T_, B_), 256>>>();
    out_kernel<<<dim3(E_ / BN, T_ / BM, B_), TB, DSMEM>>>(out);
}

// round 9
// speedup vs baseline: 8.7979x; 1.0561x over previous
#include <cuda_runtime.h>
#include <cuda_fp16.h>

#define B_ 8
#define T_ 2048
#define E_ 1024
#define M_ (B_ * T_)

#define BM 128
#define BN 128
#define BK 64
#define TB 256
#define NSTAGE 3
#define ASUB 16384u                      // 128x64 fp16
#define STAGE_BYTES (2 * ASUB)           // 32768
#define DSMEM (NSTAGE * STAGE_BYTES)     // 98304
#define QK_SCALE 0.17677669529663687f    // 1024^-0.25

// ---------------- scratch ----------------
__device__ __half g_x[3][(size_t)M_ * E_];
__device__ __half g_w[3][(size_t)E_ * E_];
__device__ __half g_Q[(size_t)M_ * E_];
__device__ __half g_K[(size_t)M_ * E_];
__device__ __half g_V[(size_t)M_ * E_];
__device__ __half g_Vt[(size_t)B_ * E_ * T_];
__device__ __half g_P[(size_t)B_ * T_ * T_];   // exp(scores), unnormalized
__device__ float  g_rinv[(size_t)M_];          // 1 / rowsum

// ---------------- helpers ----------------
__device__ __forceinline__ unsigned smem_u32(const void* p) {
    return (unsigned)__cvta_generic_to_shared(p);
}
// 128B rows, 8x16B chunks, SW128 xor swizzle: conflict-free for ldmatrix
__device__ __forceinline__ unsigned swz128(int r, int c) {
    return (unsigned)(r * 128 + ((c ^ (r & 7)) * 16));
}
__device__ __forceinline__ void cp_async16(unsigned s, const void* g) {
    asm volatile("cp.async.cg.shared.global [%0], [%1], 16;" :: "r"(s), "l"(g) : "memory");
}
__device__ __forceinline__ void ldsm4(unsigned* r, unsigned addr) {
    asm volatile("ldmatrix.sync.aligned.m8n8.x4.shared.b16 {%0,%1,%2,%3}, [%4];"
                 : "=r"(r[0]), "=r"(r[1]), "=r"(r[2]), "=r"(r[3]) : "r"(addr));
}
__device__ __forceinline__ void mma16816(float* c, const unsigned* a, unsigned b0, unsigned b1) {
    asm volatile(
        "mma.sync.aligned.m16n8k16.row.col.f32.f16.f16.f32 "
        "{%0,%1,%2,%3}, {%4,%5,%6,%7}, {%8,%9}, {%0,%1,%2,%3};"
        : "+f"(c[0]), "+f"(c[1]), "+f"(c[2]), "+f"(c[3])
        : "r"(a[0]), "r"(a[1]), "r"(a[2]), "r"(a[3]), "r"(b0), "r"(b1));
}

// ---------------- single-pass fp16 mma.sync GEMM body (128x128 tile) --------
// D[m0..+128, n0..+128] = A * B^T (both fp16, K-major). Warp tile 64x32.
// EPI 2: scale + fp16 to Ch
// EPI 3: exp(v) with causal mask (col > row -> 0), fp16 to Ch
// EPI 4: fp32 to Cf, scaled by Rinv[row]
template <int EPI>
__device__ __forceinline__ void gemm_body(
    const __half* __restrict__ A, const __half* __restrict__ Bs,
    int lda, int ldb, int m0, int n0, int kTiles, float scale,
    float* __restrict__ Cf, __half* __restrict__ Ch, int ldc,
    const float* __restrict__ Rinv)
{
    extern __shared__ __align__(128) char smem[];
    const unsigned sbase = smem_u32(smem);
    const int tid = threadIdx.x;
    const int wid = tid >> 5;
    const int lane = tid & 31;
    const int wm = wid & 1;        // 2 m-tiles of 64
    const int wn = wid >> 1;       // 4 n-tiles of 32

    // per-ks base ldmatrix offsets; row +16 adds exactly 2048 bytes (swizzle-safe)
    unsigned abase[4], bbase[4];
#pragma unroll
    for (int ks = 0; ks < 4; ++ks) {
        abase[ks] = swz128(wm * 64 + (lane & 15), ks * 2 + (lane >> 4));
        bbase[ks] = ASUB + swz128(wn * 32 + ((lane >> 4) & 1) * 8 + (lane & 7),
                                  ks * 2 + ((lane >> 3) & 1));
    }

    float acc[4][4][4];
#pragma unroll
    for (int i = 0; i < 4; ++i)
#pragma unroll
        for (int j = 0; j < 4; ++j)
#pragma unroll
            for (int e = 0; e < 4; ++e) acc[i][j][e] = 0.0f;

    const int cc = tid & 7;        // chunk within row
    const int rr = tid >> 3;       // base row (0..31)

    auto load_stage = [&](int k0, int buf) {
        const unsigned sb = sbase + buf * STAGE_BYTES;
#pragma unroll
        for (int j = 0; j < 4; ++j) {          // A: 128 rows
            const int r = rr + j * 32;
            cp_async16(sb + swz128(r, cc),
                       A + (size_t)(m0 + r) * lda + k0 + cc * 8);
        }
#pragma unroll
        for (int j = 0; j < 4; ++j) {          // B: 128 rows
            const int r = rr + j * 32;
            cp_async16(sb + ASUB + swz128(r, cc),
                       Bs + (size_t)(n0 + r) * ldb + k0 + cc * 8);
        }
    };

    auto compute_ks = [&](unsigned sb, int ks) {
        unsigned a[4][4], b[2][4];
#pragma unroll
        for (int mi = 0; mi < 4; ++mi) ldsm4(a[mi], sb + abase[ks] + mi * 2048);
#pragma unroll
        for (int jp = 0; jp < 2; ++jp) ldsm4(b[jp], sb + bbase[ks] + jp * 2048);
#pragma unroll
        for (int mi = 0; mi < 4; ++mi)
#pragma unroll
            for (int ni = 0; ni < 4; ++ni)
                mma16816(acc[mi][ni], a[mi],
                         b[ni >> 1][(ni & 1) * 2], b[ni >> 1][(ni & 1) * 2 + 1]);
    };

    load_stage(0, 0);
    asm volatile("cp.async.commit_group;" ::: "memory");
    if (kTiles > 1) load_stage(BK, 1);
    asm volatile("cp.async.commit_group;" ::: "memory");

    for (int it = 0; it < kTiles; ++it) {
        asm volatile("cp.async.wait_group 1;" ::: "memory");
        __syncthreads();
        const unsigned sb = sbase + (it % NSTAGE) * STAGE_BYTES;
        compute_ks(sb, 0);
        if (it + 2 < kTiles) load_stage((it + 2) * BK, (it + 2) % NSTAGE);
        asm volatile("cp.async.commit_group;" ::: "memory");
        compute_ks(sb, 1);
        compute_ks(sb, 2);
        compute_ks(sb, 3);
    }

    // epilogue
    const int g = lane >> 2, tig = lane & 3;
#pragma unroll
    for (int mi = 0; mi < 4; ++mi) {
#pragma unroll
        for (int ni = 0; ni < 4; ++ni) {
            const int row = m0 + wm * 64 + mi * 16 + g;
            const int col = n0 + wn * 32 + ni * 8 + tig * 2;
#pragma unroll
            for (int h = 0; h < 2; ++h) {
                const int r = row + h * 8;
                float v0 = acc[mi][ni][2 * h + 0];
                float v1 = acc[mi][ni][2 * h + 1];
                if (EPI == 2) {
                    __half2 hh;
                    hh.x = __float2half(v0 * scale);
                    hh.y = __float2half(v1 * scale);
                    *(__half2*)(Ch + (size_t)r * ldc + col) = hh;
                } else if (EPI == 3) {
                    __half2 hh;
                    hh.x = (col     <= r) ? __float2half(__expf(v0)) : __half(0.0f);
                    hh.y = (col + 1 <= r) ? __float2half(__expf(v1)) : __half(0.0f);
                    *(__half2*)(Ch + (size_t)r * ldc + col) = hh;
                } else {
                    const float rv = Rinv[r];
                    *(float2*)(Cf + (size_t)r * ldc + col) = make_float2(v0 * rv, v1 * rv);
                }
            }
        }
    }
}

// ---------------- kernels ----------------
__global__ void __launch_bounds__(TB, 2)
proj_kernel()
{
    const int z = blockIdx.z;
    const int m0 = blockIdx.y * BM;
    const int n0 = blockIdx.x * BN;
    __half* dst = (z == 0) ? g_Q : (z == 1) ? g_K : g_V;
    const float scale = (z < 2) ? QK_SCALE : 1.0f;
    gemm_body<2>(g_x[z], g_w[z], E_, E_, m0, n0, E_ / BK, scale, nullptr, dst, E_, nullptr);
}

__global__ void __launch_bounds__(TB, 2)
scores_kernel()
{
    if ((int)blockIdx.x > (int)blockIdx.y) return;   // fully above causal diagonal
    const int b = blockIdx.z;
    const size_t qo = (size_t)b * T_ * E_;
    gemm_body<3>(g_Q + qo, g_K + qo, E_, E_,
                 blockIdx.y * BM, blockIdx.x * BN, E_ / BK, 1.0f,
                 nullptr, g_P + (size_t)b * T_ * T_, T_, nullptr);
}

__global__ void __launch_bounds__(TB, 2)
out_kernel(float* __restrict__ out)
{
    const int b = blockIdx.z;
    // reversed y: heaviest (largest-kT) blocks get the lowest block ids -> start first
    const int m0 = ((int)gridDim.y - 1 - (int)blockIdx.y) * BM;
    const int kT = (m0 + BM) / BK;   // causal clamp: P cols beyond m0+127 are zero
    gemm_body<4>(g_P + (size_t)b * T_ * T_, g_Vt + (size_t)b * E_ * T_,
                 T_, T_, m0, blockIdx.x * BN, kT, 1.0f,
                 out + (size_t)b * T_ * E_, nullptr, E_, g_rinv + (size_t)b * T_);
}

__global__ void __launch_bounds__(256)
convert3_kernel(const float* __restrict__ a, const float* __restrict__ b,
                const float* __restrict__ c, __half* __restrict__ o0,
                __half* __restrict__ o1, __half* __restrict__ o2, int n4)
{
    const float* in = (blockIdx.z == 0) ? a : (blockIdx.z == 1) ? b : c;
    __half* out = (blockIdx.z == 0) ? o0 : (blockIdx.z == 1) ? o1 : o2;
    int i = blockIdx.x * blockDim.x + threadIdx.x;
    const int stride = gridDim.x * blockDim.x;
    for (; i < n4; i += stride) {
        float4 x = ((const float4*)in)[i];
        __half2 h0; h0.x = __float2half(x.x); h0.y = __float2half(x.y);
        __half2 h1; h1.x = __float2half(x.z); h1.y = __float2half(x.w);
        ((__half2*)out)[2 * i] = h0;
        ((__half2*)out)[2 * i + 1] = h1;
    }
}

// 64x64 tile, half2 vectorized both sides
__global__ void __launch_bounds__(256)
transpose_v_kernel()
{
    __shared__ __half tile[64][65];
    const int b = blockIdx.z;
    const int e0 = blockIdx.x * 64;
    const int t0 = blockIdx.y * 64;
    const int tx = threadIdx.x & 31;   // half2 column index
    const int ty = threadIdx.x >> 5;   // 0..7
    const __half2* src2 = (const __half2*)(g_V + (size_t)b * T_ * E_);
#pragma unroll
    for (int k = 0; k < 8; ++k) {
        int row = ty + k * 8;                       // t offset
        __half2 v = src2[((size_t)(t0 + row) * E_ + e0) / 2 + tx];
        tile[row][2 * tx]     = v.x;
        tile[row][2 * tx + 1] = v.y;
    }
    __syncthreads();
    __half2* dst2 = (__half2*)(g_Vt + (size_t)b * E_ * T_);
#pragma unroll
    for (int k = 0; k < 8; ++k) {
        int erow = ty + k * 8;                      // e offset
        __half2 w;
        w.x = tile[2 * tx][erow];
        w.y = tile[2 * tx + 1][erow];
        dst2[((size_t)(e0 + erow) * T_ + t0) / 2 + tx] = w;
    }
}

// 1 / sum of each row of g_P (valid length = row + 1; tail is zero anyway)
__global__ void __launch_bounds__(256)
rowsum_kernel()
{
    const int i = blockIdx.x;
    const int b = blockIdx.y;
    const __half* ph = g_P + ((size_t)b * T_ + i) * T_;
    const int L = i + 1;
    const int tid = threadIdx.x;
    __shared__ float red[8];

    float s = 0.0f;
    for (int j = tid; j < L; j += 256) s += __half2float(ph[j]);
#pragma unroll
    for (int o = 16; o > 0; o >>= 1) s += __shfl_xor_sync(0xffffffffu, s, o);
    if ((tid & 31) == 0) red[tid >> 5] = s;
    __syncthreads();
    if (tid == 0) {
        float ss = 0.0f;
#pragma unroll
        for (int w = 0; w < 8; ++w) ss += red[w];
        g_rinv[(size_t)b * T_ + i] = 1.0f / ss;
    }
}

// ---------------- launch ----------------
extern "C" void kernel_launch(void* const* d_in, const int* in_sizes, int n_in,
                              void* d_out, int out_size)
{
    const float* q  = (const float*)d_in[0];
    const float* k  = (const float*)d_in[1];
    const float* v  = (const float*)d_in[2];
    const float* Wq = (const float*)d_in[3];
    const float* Wk = (const float*)d_in[4];
    const float* Wv = (const float*)d_in[5];
    float* out = (float*)d_out;

    cudaFuncSetAttribute(proj_kernel,   cudaFuncAttributeMaxDynamicSharedMemorySize, DSMEM);
    cudaFuncSetAttribute(scores_kernel, cudaFuncAttributeMaxDynamicSharedMemorySize, DSMEM);
    cudaFuncSetAttribute(out_kernel,    cudaFuncAttributeMaxDynamicSharedMemorySize, DSMEM);

    __half *x0, *w0;
    cudaGetSymbolAddress((void**)&x0, g_x);
    cudaGetSymbolAddress((void**)&w0, g_w);
    __half *x1 = x0 + (size_t)M_ * E_, *x2 = x1 + (size_t)M_ * E_;
    __half *w1 = w0 + (size_t)E_ * E_, *w2 = w1 + (size_t)E_ * E_;

    const int n4x = M_ * E_ / 4;
    const int n4w = E_ * E_ / 4;
    convert3_kernel<<<dim3(1024, 1, 3), 256>>>(q, k, v, x0, x1, x2, n4x);
    convert3_kernel<<<dim3(256, 1, 3), 256>>>(Wq, Wk, Wv, w0, w1, w2, n4w);

    proj_kernel<<<dim3(E_ / BN, M_ / BM, 3), TB, DSMEM>>>();
    transpose_v_kernel<<<dim3(E_ / 64, T_ / 64, B_), 256>>>();
    scores_kernel<<<dim3(T_ / BN, T_ / BM, B_), TB, DSMEM>>>();
    rowsum_kernel<<<dim3(T_, B_), 256>>>();
    out_kernel<<<dim3(E_ / BN, T_ / BM, B_), TB, DSMEM>>>(out);
}

// round 10
// speedup vs baseline: 8.8174x; 1.0022x over previous
#include <cuda_runtime.h>
#include <cuda_fp16.h>

#define B_ 8
#define T_ 2048
#define E_ 1024
#define M_ (B_ * T_)

#define BM 128
#define BN 128
#define BK 64
#define TB 256
#define NSTAGE 3
#define ASUB 16384u                      // 128x64 fp16
#define STAGE_BYTES (2 * ASUB)           // 32768
#define DSMEM (NSTAGE * STAGE_BYTES)     // 98304
#define QK_SCALE 0.17677669529663687f    // 1024^-0.25

// ---------------- scratch ----------------
__device__ __half g_x[3][(size_t)M_ * E_];
__device__ __half g_w[3][(size_t)E_ * E_];
__device__ __half g_Q[(size_t)M_ * E_];
__device__ __half g_K[(size_t)M_ * E_];
__device__ __half g_V[(size_t)M_ * E_];
__device__ __half g_Vt[(size_t)B_ * E_ * T_];
__device__ __half g_P[(size_t)B_ * T_ * T_];   // exp(scores), unnormalized
__device__ float  g_rinv[(size_t)M_];          // 1 / rowsum

// ---------------- helpers ----------------
__device__ __forceinline__ unsigned smem_u32(const void* p) {
    return (unsigned)__cvta_generic_to_shared(p);
}
// 128B rows, 8x16B chunks, SW128 xor swizzle: conflict-free for ldmatrix
__device__ __forceinline__ unsigned swz128(int r, int c) {
    return (unsigned)(r * 128 + ((c ^ (r & 7)) * 16));
}
__device__ __forceinline__ void cp_async16(unsigned s, const void* g) {
    asm volatile("cp.async.cg.shared.global [%0], [%1], 16;" :: "r"(s), "l"(g) : "memory");
}
__device__ __forceinline__ void ldsm4(unsigned* r, unsigned addr) {
    asm volatile("ldmatrix.sync.aligned.m8n8.x4.shared.b16 {%0,%1,%2,%3}, [%4];"
                 : "=r"(r[0]), "=r"(r[1]), "=r"(r[2]), "=r"(r[3]) : "r"(addr));
}
__device__ __forceinline__ void mma16816(float* c, const unsigned* a, unsigned b0, unsigned b1) {
    asm volatile(
        "mma.sync.aligned.m16n8k16.row.col.f32.f16.f16.f32 "
        "{%0,%1,%2,%3}, {%4,%5,%6,%7}, {%8,%9}, {%0,%1,%2,%3};"
        : "+f"(c[0]), "+f"(c[1]), "+f"(c[2]), "+f"(c[3])
        : "r"(a[0]), "r"(a[1]), "r"(a[2]), "r"(a[3]), "r"(b0), "r"(b1));
}

// ---------------- single-pass fp16 mma.sync GEMM body (128x128 tile) --------
// D[m0..+128, n0..+128] = A * B^T (both fp16, K-major). Warp tile 64x32.
// EPI 2: scale + fp16 to Ch
// EPI 3: exp(v) with causal mask (col > row -> 0), fp16 to Ch
// EPI 4: fp32 to Cf, scaled by Rinv[row]
template <int EPI>
__device__ __forceinline__ void gemm_body(
    const __half* __restrict__ A, const __half* __restrict__ Bs,
    int lda, int ldb, int m0, int n0, int kTiles, float scale,
    float* __restrict__ Cf, __half* __restrict__ Ch, int ldc,
    const float* __restrict__ Rinv)
{
    extern __shared__ __align__(128) char smem[];
    const unsigned sbase = smem_u32(smem);
    const int tid = threadIdx.x;
    const int wid = tid >> 5;
    const int lane = tid & 31;
    const int wm = wid & 1;        // 2 m-tiles of 64
    const int wn = wid >> 1;       // 4 n-tiles of 32

    // per-ks base ldmatrix offsets; row +16 adds exactly 2048 bytes (swizzle-safe)
    unsigned abase[4], bbase[4];
#pragma unroll
    for (int ks = 0; ks < 4; ++ks) {
        abase[ks] = swz128(wm * 64 + (lane & 15), ks * 2 + (lane >> 4));
        bbase[ks] = ASUB + swz128(wn * 32 + ((lane >> 4) & 1) * 8 + (lane & 7),
                                  ks * 2 + ((lane >> 3) & 1));
    }

    float acc[4][4][4];
#pragma unroll
    for (int i = 0; i < 4; ++i)
#pragma unroll
        for (int j = 0; j < 4; ++j)
#pragma unroll
            for (int e = 0; e < 4; ++e) acc[i][j][e] = 0.0f;

    const int cc = tid & 7;        // chunk within row
    const int rr = tid >> 3;       // base row (0..31)

    auto load_stage = [&](int k0, int buf) {
        const unsigned sb = sbase + buf * STAGE_BYTES;
#pragma unroll
        for (int j = 0; j < 4; ++j) {          // A: 128 rows
            const int r = rr + j * 32;
            cp_async16(sb + swz128(r, cc),
                       A + (size_t)(m0 + r) * lda + k0 + cc * 8);
        }
#pragma unroll
        for (int j = 0; j < 4; ++j) {          // B: 128 rows
            const int r = rr + j * 32;
            cp_async16(sb + ASUB + swz128(r, cc),
                       Bs + (size_t)(n0 + r) * ldb + k0 + cc * 8);
        }
    };

    auto compute_ks = [&](unsigned sb, int ks) {
        unsigned a[4][4], b[2][4];
#pragma unroll
        for (int mi = 0; mi < 4; ++mi) ldsm4(a[mi], sb + abase[ks] + mi * 2048);
#pragma unroll
        for (int jp = 0; jp < 2; ++jp) ldsm4(b[jp], sb + bbase[ks] + jp * 2048);
#pragma unroll
        for (int mi = 0; mi < 4; ++mi)
#pragma unroll
            for (int ni = 0; ni < 4; ++ni)
                mma16816(acc[mi][ni], a[mi],
                         b[ni >> 1][(ni & 1) * 2], b[ni >> 1][(ni & 1) * 2 + 1]);
    };

    load_stage(0, 0);
    asm volatile("cp.async.commit_group;" ::: "memory");
    if (kTiles > 1) load_stage(BK, 1);
    asm volatile("cp.async.commit_group;" ::: "memory");

    for (int it = 0; it < kTiles; ++it) {
        asm volatile("cp.async.wait_group 1;" ::: "memory");
        __syncthreads();
        const unsigned sb = sbase + (it % NSTAGE) * STAGE_BYTES;
        compute_ks(sb, 0);
        if (it + 2 < kTiles) load_stage((it + 2) * BK, (it + 2) % NSTAGE);
        asm volatile("cp.async.commit_group;" ::: "memory");
        compute_ks(sb, 1);
        compute_ks(sb, 2);
        compute_ks(sb, 3);
    }

    // epilogue
    const int g = lane >> 2, tig = lane & 3;
#pragma unroll
    for (int mi = 0; mi < 4; ++mi) {
#pragma unroll
        for (int ni = 0; ni < 4; ++ni) {
            const int row = m0 + wm * 64 + mi * 16 + g;
            const int col = n0 + wn * 32 + ni * 8 + tig * 2;
#pragma unroll
            for (int h = 0; h < 2; ++h) {
                const int r = row + h * 8;
                float v0 = acc[mi][ni][2 * h + 0];
                float v1 = acc[mi][ni][2 * h + 1];
                if (EPI == 2) {
                    __half2 hh;
                    hh.x = __float2half(v0 * scale);
                    hh.y = __float2half(v1 * scale);
                    *(__half2*)(Ch + (size_t)r * ldc + col) = hh;
                } else if (EPI == 3) {
                    __half2 hh;
                    hh.x = (col     <= r) ? __float2half(__expf(v0)) : __half(0.0f);
                    hh.y = (col + 1 <= r) ? __float2half(__expf(v1)) : __half(0.0f);
                    *(__half2*)(Ch + (size_t)r * ldc + col) = hh;
                } else {
                    const float rv = Rinv[r];
                    *(float2*)(Cf + (size_t)r * ldc + col) = make_float2(v0 * rv, v1 * rv);
                }
            }
        }
    }
}

// ---------------- kernels ----------------
__global__ void __launch_bounds__(TB, 2)
proj_kernel()
{
    const int z = blockIdx.z;
    const int m0 = blockIdx.y * BM;
    const int n0 = blockIdx.x * BN;
    __half* dst = (z == 0) ? g_Q : (z == 1) ? g_K : g_V;
    const float scale = (z < 2) ? QK_SCALE : 1.0f;
    gemm_body<2>(g_x[z], g_w[z], E_, E_, m0, n0, E_ / BK, scale, nullptr, dst, E_, nullptr);
}

__global__ void __launch_bounds__(TB, 2)
scores_kernel()
{
    if ((int)blockIdx.x > (int)blockIdx.y) return;   // fully above causal diagonal
    const int b = blockIdx.z;
    const size_t qo = (size_t)b * T_ * E_;
    gemm_body<3>(g_Q + qo, g_K + qo, E_, E_,
                 blockIdx.y * BM, blockIdx.x * BN, E_ / BK, 1.0f,
                 nullptr, g_P + (size_t)b * T_ * T_, T_, nullptr);
}

__global__ void __launch_bounds__(TB, 2)
out_kernel(float* __restrict__ out)
{
    const int b = blockIdx.z;
    // reversed y: heaviest (largest-kT) blocks get the lowest block ids -> start first
    const int m0 = ((int)gridDim.y - 1 - (int)blockIdx.y) * BM;
    const int kT = (m0 + BM) / BK;   // causal clamp: P cols beyond m0+127 are zero
    gemm_body<4>(g_P + (size_t)b * T_ * T_, g_Vt + (size_t)b * E_ * T_,
                 T_, T_, m0, blockIdx.x * BN, kT, 1.0f,
                 out + (size_t)b * T_ * E_, nullptr, E_, g_rinv + (size_t)b * T_);
}

__global__ void __launch_bounds__(256)
convert3_kernel(const float* __restrict__ a, const float* __restrict__ b,
                const float* __restrict__ c, __half* __restrict__ o0,
                __half* __restrict__ o1, __half* __restrict__ o2, int n4)
{
    const float* in = (blockIdx.z == 0) ? a : (blockIdx.z == 1) ? b : c;
    __half* out = (blockIdx.z == 0) ? o0 : (blockIdx.z == 1) ? o1 : o2;
    int i = blockIdx.x * blockDim.x + threadIdx.x;
    const int stride = gridDim.x * blockDim.x;
    for (; i < n4; i += stride) {
        float4 x = ((const float4*)in)[i];
        __half2 h0; h0.x = __float2half(x.x); h0.y = __float2half(x.y);
        __half2 h1; h1.x = __float2half(x.z); h1.y = __float2half(x.w);
        ((__half2*)out)[2 * i] = h0;
        ((__half2*)out)[2 * i + 1] = h1;
    }
}

// 64x64 tile, half2 vectorized both sides
__global__ void __launch_bounds__(256)
transpose_v_kernel()
{
    __shared__ __half tile[64][65];
    const int b = blockIdx.z;
    const int e0 = blockIdx.x * 64;
    const int t0 = blockIdx.y * 64;
    const int tx = threadIdx.x & 31;   // half2 column index
    const int ty = threadIdx.x >> 5;   // 0..7
    const __half2* src2 = (const __half2*)(g_V + (size_t)b * T_ * E_);
#pragma unroll
    for (int k = 0; k < 8; ++k) {
        int row = ty + k * 8;                       // t offset
        __half2 v = src2[((size_t)(t0 + row) * E_ + e0) / 2 + tx];
        tile[row][2 * tx]     = v.x;
        tile[row][2 * tx + 1] = v.y;
    }
    __syncthreads();
    __half2* dst2 = (__half2*)(g_Vt + (size_t)b * E_ * T_);
#pragma unroll
    for (int k = 0; k < 8; ++k) {
        int erow = ty + k * 8;                      // e offset
        __half2 w;
        w.x = tile[2 * tx][erow];
        w.y = tile[2 * tx + 1][erow];
        dst2[((size_t)(e0 + erow) * T_ + t0) / 2 + tx] = w;
    }
}

// 1 / sum of each row of g_P (valid length = row + 1; tail is zero anyway)
__global__ void __launch_bounds__(256)
rowsum_kernel()
{
    const int i = blockIdx.x;
    const int b = blockIdx.y;
    const __half* ph = g_P + ((size_t)b * T_ + i) * T_;
    const int L = i + 1;
    const int tid = threadIdx.x;
    __shared__ float red[8];

    float s = 0.0f;
    for (int j = tid; j < L; j += 256) s += __half2float(ph[j]);
#pragma unroll
    for (int o = 16; o > 0; o >>= 1) s += __shfl_xor_sync(0xffffffffu, s, o);
    if ((tid & 31) == 0) red[tid >> 5] = s;
    __syncthreads();
    if (tid == 0) {
        float ss = 0.0f;
#pragma unroll
        for (int w = 0; w < 8; ++w) ss += red[w];
        g_rinv[(size_t)b * T_ + i] = 1.0f / ss;
    }
}

// ---------------- launch ----------------
extern "C" void kernel_launch(void* const* d_in, const int* in_sizes, int n_in,
                              void* d_out, int out_size)
{
    const float* q  = (const float*)d_in[0];
    const float* k  = (const float*)d_in[1];
    const float* v  = (const float*)d_in[2];
    const float* Wq = (const float*)d_in[3];
    const float* Wk = (const float*)d_in[4];
    const float* Wv = (const float*)d_in[5];
    float* out = (float*)d_out;

    cudaFuncSetAttribute(proj_kernel,   cudaFuncAttributeMaxDynamicSharedMemorySize, DSMEM);
    cudaFuncSetAttribute(scores_kernel, cudaFuncAttributeMaxDynamicSharedMemorySize, DSMEM);
    cudaFuncSetAttribute(out_kernel,    cudaFuncAttributeMaxDynamicSharedMemorySize, DSMEM);

    __half *x0, *w0;
    cudaGetSymbolAddress((void**)&x0, g_x);
    cudaGetSymbolAddress((void**)&w0, g_w);
    __half *x1 = x0 + (size_t)M_ * E_, *x2 = x1 + (size_t)M_ * E_;
    __half *w1 = w0 + (size_t)E_ * E_, *w2 = w1 + (size_t)E_ * E_;

    const int n4x = M_ * E_ / 4;
    const int n4w = E_ * E_ / 4;
    convert3_kernel<<<dim3(1024, 1, 3), 256>>>(q, k, v, x0, x1, x2, n4x);
    convert3_kernel<<<dim3(256, 1, 3), 256>>>(Wq, Wk, Wv, w0, w1, w2, n4w);

    proj_kernel<<<dim3(E_ / BN, M_ / BM, 3), TB, DSMEM>>>();
    transpose_v_kernel<<<dim3(E_ / 64, T_ / 64, B_), 256>>>();
    scores_kernel<<<dim3(T_ / BN, T_ / BM, B_), TB, DSMEM>>>();
    rowsum_kernel<<<dim3(T_, B_), 256>>>();
    out_kernel<<<dim3(E_ / BN, T_ / BM, B_), TB, DSMEM>>>(out);
}